// round 1
// baseline (speedup 1.0000x reference)
#include <cuda_runtime.h>
#include <cuda_bf16.h>
#include <math.h>
#include <stdint.h>

// ---------------------------------------------------------------------------
// Problem constants
// ---------------------------------------------------------------------------
#define SEQ     2048
#define HID     2048
#define NHEADS  16
#define QLORA   1536
#define KVLORA  512
#define DROPE   64
#define DNOPE   128
#define DVDIM   128
#define QHD     192              // DNOPE + DROPE
#define QROW    (NHEADS*QHD)     // 3072
#define KVROW   (NHEADS*(DNOPE+DVDIM)) // 4096
#define CKVROW  (KVLORA+DROPE)   // 576

// ---------------------------------------------------------------------------
// Scratch (device globals; allocation-free per harness rules)
// ---------------------------------------------------------------------------
__device__ float g_qa  [SEQ*QLORA];   // x @ wq_a  (rmsnormed in-place)
__device__ float g_q   [SEQ*QROW];    // q (roped in-place)
__device__ float g_ckv [SEQ*CKVROW];  // x @ wkv_a
__device__ float g_kvn [SEQ*KVLORA];  // rmsnorm(ckv[:, :512])
__device__ float g_kpe [SEQ*DROPE];   // roped k_pe
__device__ float g_kv  [SEQ*KVROW];   // kvn @ wkv_b
__device__ float g_attn[SEQ*HID];     // attention output (heads concat)

// ---------------------------------------------------------------------------
// SGEMM: C[M,N] = A[M,K] * B[K,N], row-major fp32. 128x128 tile, BK=8,
// 256 threads, 8x8 per thread. M assumed multiple of 128, K multiple of 8,
// N guarded (N multiple of 4).
// ---------------------------------------------------------------------------
__global__ __launch_bounds__(256) void sgemm_k(
    const float* __restrict__ A, const float* __restrict__ B,
    float* __restrict__ C, int M, int N, int K)
{
    __shared__ float As[8][128];
    __shared__ float Bs[8][128];

    const int tid = threadIdx.x;
    const int tx = tid & 15;          // 0..15 -> col group
    const int ty = tid >> 4;          // 0..15 -> row group
    const int blockRow = blockIdx.y * 128;
    const int blockCol = blockIdx.x * 128;

    float acc[8][8];
#pragma unroll
    for (int i = 0; i < 8; i++)
#pragma unroll
        for (int j = 0; j < 8; j++) acc[i][j] = 0.f;

    for (int k0 = 0; k0 < K; k0 += 8) {
        // load A tile (128 rows x 8 k), transposed into As[k][row]
        {
            const int row = tid >> 1;
            const int kk  = (tid & 1) * 4;
            const int gr  = blockRow + row;
            float4 v = *reinterpret_cast<const float4*>(&A[(size_t)gr * K + k0 + kk]);
            As[kk + 0][row] = v.x;
            As[kk + 1][row] = v.y;
            As[kk + 2][row] = v.z;
            As[kk + 3][row] = v.w;
        }
        // load B tile (8 k x 128 cols)
        {
            const int kk  = tid >> 5;
            const int col = (tid & 31) * 4;
            const int gc  = blockCol + col;
            float4 v = make_float4(0.f, 0.f, 0.f, 0.f);
            if (gc < N)
                v = *reinterpret_cast<const float4*>(&B[(size_t)(k0 + kk) * N + gc]);
            *reinterpret_cast<float4*>(&Bs[kk][col]) = v;
        }
        __syncthreads();

#pragma unroll
        for (int kk = 0; kk < 8; kk++) {
            float a[8], b[8];
#pragma unroll
            for (int i = 0; i < 8; i++) a[i] = As[kk][ty * 8 + i];
#pragma unroll
            for (int j = 0; j < 8; j++) b[j] = Bs[kk][tx * 8 + j];
#pragma unroll
            for (int i = 0; i < 8; i++)
#pragma unroll
                for (int j = 0; j < 8; j++)
                    acc[i][j] = fmaf(a[i], b[j], acc[i][j]);
        }
        __syncthreads();
    }

#pragma unroll
    for (int i = 0; i < 8; i++) {
        const int gr = blockRow + ty * 8 + i;
#pragma unroll
        for (int j = 0; j < 8; j++) {
            const int gc = blockCol + tx * 8 + j;
            if (gc < N) C[(size_t)gr * N + gc] = acc[i][j];
        }
    }
}

// ---------------------------------------------------------------------------
// RMSNorm: one block per row.
// ---------------------------------------------------------------------------
__global__ __launch_bounds__(256) void rmsnorm_k(
    const float* __restrict__ in, int istride,
    float* __restrict__ out, int ostride,
    int dim, const float* __restrict__ w)
{
    const int row = blockIdx.x;
    const float* x = in + (size_t)row * istride;
    float* y = out + (size_t)row * ostride;

    float ss = 0.f;
    for (int i = threadIdx.x; i < dim; i += blockDim.x) {
        float v = x[i];
        ss = fmaf(v, v, ss);
    }
#pragma unroll
    for (int o = 16; o; o >>= 1) ss += __shfl_xor_sync(0xffffffffu, ss, o);

    __shared__ float red[8];
    if ((threadIdx.x & 31) == 0) red[threadIdx.x >> 5] = ss;
    __syncthreads();
    __shared__ float s_rstd;
    if (threadIdx.x == 0) {
        float v = 0.f;
        for (int i = 0; i < 8; i++) v += red[i];
        s_rstd = rsqrtf(v / (float)dim + 1e-6f);
    }
    __syncthreads();
    const float rstd = s_rstd;
    for (int i = threadIdx.x; i < dim; i += blockDim.x)
        y[i] = x[i] * rstd * w[i];
}

// ---------------------------------------------------------------------------
// RoPE on q_pe (in-place inside g_q). grid = SEQ, block = 512 (16 heads x 32)
// ---------------------------------------------------------------------------
__global__ __launch_bounds__(512) void rope_q_k(float* __restrict__ q)
{
    const int t = blockIdx.x;
    const int h = threadIdx.x >> 5;
    const int i = threadIdx.x & 31;

    const float inv = powf(10000.f, -(float)i / 32.f);
    float s, c;
    sincosf((float)t * inv, &s, &c);

    float* base = q + (size_t)t * QROW + h * QHD + DNOPE;
    const float x1 = base[i];
    const float x2 = base[i + 32];
    base[i]      = x1 * c - x2 * s;
    base[i + 32] = x2 * c + x1 * s;
}

// RoPE on k_pe: read from ckv tail, write to g_kpe. grid = SEQ, block = 32
__global__ __launch_bounds__(32) void rope_k_k(
    const float* __restrict__ ckv, float* __restrict__ kpe)
{
    const int t = blockIdx.x;
    const int i = threadIdx.x;

    const float inv = powf(10000.f, -(float)i / 32.f);
    float s, c;
    sincosf((float)t * inv, &s, &c);

    const float x1 = ckv[(size_t)t * CKVROW + KVLORA + i];
    const float x2 = ckv[(size_t)t * CKVROW + KVLORA + 32 + i];
    kpe[(size_t)t * DROPE + i]      = x1 * c - x2 * s;
    kpe[(size_t)t * DROPE + 32 + i] = x2 * c + x1 * s;
}

// ---------------------------------------------------------------------------
// Flash attention (causal), fp32 SIMT.
// grid = (SEQ/64, NHEADS), block = 256 (16x16 thread grid).
// Each thread: 4x4 S-fragment, 4x8 O-fragment.
// smem: Qs[64][196], Ks[64][196], Vs[64][132], Ps[64][68]
// ---------------------------------------------------------------------------
#define QS_STRIDE 196
#define KS_STRIDE 196
#define VS_STRIDE 132
#define PS_STRIDE 68
#define ATTN_SMEM ((64*QS_STRIDE + 64*KS_STRIDE + 64*VS_STRIDE + 64*PS_STRIDE) * 4)

__global__ __launch_bounds__(256) void mla_attn_k(
    const float* __restrict__ q, const float* __restrict__ kv,
    const float* __restrict__ kpe, float* __restrict__ out)
{
    extern __shared__ float sm[];
    float* Qs = sm;
    float* Ks = Qs + 64 * QS_STRIDE;
    float* Vs = Ks + 64 * KS_STRIDE;
    float* Ps = Vs + 64 * VS_STRIDE;

    const int h  = blockIdx.y;
    const int qb = blockIdx.x;
    const int tid = threadIdx.x;
    const int tx = tid & 15;
    const int ty = tid >> 4;

    const float scale = rsqrtf((float)QHD);   // 192^-0.5

    // load Q tile (scaled)
    for (int idx = tid; idx < 64 * QHD; idx += 256) {
        const int r = idx / QHD, d = idx % QHD;
        Qs[r * QS_STRIDE + d] =
            q[(size_t)(qb * 64 + r) * QROW + h * QHD + d] * scale;
    }

    float m[4], l[4], O[4][8];
#pragma unroll
    for (int i = 0; i < 4; i++) {
        m[i] = -INFINITY; l[i] = 0.f;
#pragma unroll
        for (int c = 0; c < 8; c++) O[i][c] = 0.f;
    }
    __syncthreads();

    for (int kb = 0; kb <= qb; kb++) {
        // load K tile: [64][192] = k_nope | k_pe(broadcast over heads)
        for (int idx = tid; idx < 64 * QHD; idx += 256) {
            const int r = idx / QHD, d = idx % QHD;
            const int cgl = kb * 64 + r;
            Ks[r * KS_STRIDE + d] = (d < DNOPE)
                ? kv[(size_t)cgl * KVROW + h * 256 + d]
                : kpe[(size_t)cgl * DROPE + (d - DNOPE)];
        }
        // load V tile: [64][128]
        for (int idx = tid; idx < 64 * DVDIM; idx += 256) {
            const int r = idx >> 7, d = idx & 127;
            const int cgl = kb * 64 + r;
            Vs[r * VS_STRIDE + d] = kv[(size_t)cgl * KVROW + h * 256 + DNOPE + d];
        }
        __syncthreads();

        // S = Q K^T
        float S[4][4];
#pragma unroll
        for (int i = 0; i < 4; i++)
#pragma unroll
            for (int j = 0; j < 4; j++) S[i][j] = 0.f;

        for (int d = 0; d < QHD; d += 4) {
            float4 a[4], b[4];
#pragma unroll
            for (int i = 0; i < 4; i++)
                a[i] = *reinterpret_cast<const float4*>(&Qs[(ty * 4 + i) * QS_STRIDE + d]);
#pragma unroll
            for (int j = 0; j < 4; j++)
                b[j] = *reinterpret_cast<const float4*>(&Ks[(tx * 4 + j) * KS_STRIDE + d]);
#pragma unroll
            for (int i = 0; i < 4; i++)
#pragma unroll
                for (int j = 0; j < 4; j++) {
                    S[i][j] = fmaf(a[i].x, b[j].x, S[i][j]);
                    S[i][j] = fmaf(a[i].y, b[j].y, S[i][j]);
                    S[i][j] = fmaf(a[i].z, b[j].z, S[i][j]);
                    S[i][j] = fmaf(a[i].w, b[j].w, S[i][j]);
                }
        }

        // causal mask (diagonal block only)
        if (kb == qb) {
            const int gr0 = qb * 64 + ty * 4;
            const int gc0 = kb * 64 + tx * 4;
#pragma unroll
            for (int i = 0; i < 4; i++)
#pragma unroll
                for (int j = 0; j < 4; j++)
                    if (gc0 + j > gr0 + i) S[i][j] = -INFINITY;
        }

        // online softmax (row stats across the 16 tx-threads of each row)
        float f[4];
#pragma unroll
        for (int i = 0; i < 4; i++) {
            float v = S[i][0];
            v = fmaxf(v, S[i][1]); v = fmaxf(v, S[i][2]); v = fmaxf(v, S[i][3]);
#pragma unroll
            for (int o = 8; o; o >>= 1) v = fmaxf(v, __shfl_xor_sync(0xffffffffu, v, o));
            const float mnew = fmaxf(m[i], v);
            f[i] = __expf(m[i] - mnew);
            m[i] = mnew;
        }
#pragma unroll
        for (int i = 0; i < 4; i++) {
            float lloc = 0.f;
#pragma unroll
            for (int j = 0; j < 4; j++) {
                const float p = __expf(S[i][j] - m[i]);
                Ps[(ty * 4 + i) * PS_STRIDE + tx * 4 + j] = p;
                lloc += p;
            }
#pragma unroll
            for (int o = 8; o; o >>= 1) lloc += __shfl_xor_sync(0xffffffffu, lloc, o);
            l[i] = l[i] * f[i] + lloc;
        }
#pragma unroll
        for (int i = 0; i < 4; i++)
#pragma unroll
            for (int c = 0; c < 8; c++) O[i][c] *= f[i];
        __syncthreads();

        // O += P @ V
        for (int j = 0; j < 64; j++) {
            float p[4];
#pragma unroll
            for (int i = 0; i < 4; i++) p[i] = Ps[(ty * 4 + i) * PS_STRIDE + j];
            const float4 v0 = *reinterpret_cast<const float4*>(&Vs[j * VS_STRIDE + tx * 8]);
            const float4 v1 = *reinterpret_cast<const float4*>(&Vs[j * VS_STRIDE + tx * 8 + 4]);
#pragma unroll
            for (int i = 0; i < 4; i++) {
                O[i][0] = fmaf(p[i], v0.x, O[i][0]);
                O[i][1] = fmaf(p[i], v0.y, O[i][1]);
                O[i][2] = fmaf(p[i], v0.z, O[i][2]);
                O[i][3] = fmaf(p[i], v0.w, O[i][3]);
                O[i][4] = fmaf(p[i], v1.x, O[i][4]);
                O[i][5] = fmaf(p[i], v1.y, O[i][5]);
                O[i][6] = fmaf(p[i], v1.z, O[i][6]);
                O[i][7] = fmaf(p[i], v1.w, O[i][7]);
            }
        }
        __syncthreads();
    }

    // epilogue: normalize and store to attn[row, h*128 + col]
#pragma unroll
    for (int i = 0; i < 4; i++) {
        const float inv = 1.f / l[i];
        const int row = qb * 64 + ty * 4 + i;
#pragma unroll
        for (int c = 0; c < 8; c++)
            out[(size_t)row * HID + h * DVDIM + tx * 8 + c] = O[i][c] * inv;
    }
}

// ---------------------------------------------------------------------------
// Launch
// ---------------------------------------------------------------------------
static inline void launch_sgemm(const float* A, const float* B, float* C,
                                int M, int N, int K)
{
    dim3 grid((N + 127) / 128, (M + 127) / 128);
    sgemm_k<<<grid, 256>>>(A, B, C, M, N, K);
}

extern "C" void kernel_launch(void* const* d_in, const int* in_sizes, int n_in,
                              void* d_out, int out_size)
{
    const float* x        = (const float*)d_in[0];
    const float* wq_a     = (const float*)d_in[1];
    const float* q_a_ln_w = (const float*)d_in[2];
    const float* wq_b     = (const float*)d_in[3];
    const float* wkv_a    = (const float*)d_in[4];
    const float* kv_a_ln_w= (const float*)d_in[5];
    const float* wkv_b    = (const float*)d_in[6];
    const float* wo       = (const float*)d_in[7];
    float* out            = (float*)d_out;

    float *qa, *qbuf, *ckv, *kvn, *kpe, *kv, *attn;
    cudaGetSymbolAddress((void**)&qa,   g_qa);
    cudaGetSymbolAddress((void**)&qbuf, g_q);
    cudaGetSymbolAddress((void**)&ckv,  g_ckv);
    cudaGetSymbolAddress((void**)&kvn,  g_kvn);
    cudaGetSymbolAddress((void**)&kpe,  g_kpe);
    cudaGetSymbolAddress((void**)&kv,   g_kv);
    cudaGetSymbolAddress((void**)&attn, g_attn);

    cudaFuncSetAttribute(mla_attn_k,
        cudaFuncAttributeMaxDynamicSharedMemorySize, ATTN_SMEM);

    // q path
    launch_sgemm(x, wq_a, qa, SEQ, QLORA, HID);                 // qa = x @ wq_a
    rmsnorm_k<<<SEQ, 256>>>(qa, QLORA, qa, QLORA, QLORA, q_a_ln_w);
    launch_sgemm(qa, wq_b, qbuf, SEQ, QROW, QLORA);             // q = qa_n @ wq_b

    // kv path
    launch_sgemm(x, wkv_a, ckv, SEQ, CKVROW, HID);              // ckv = x @ wkv_a
    rmsnorm_k<<<SEQ, 256>>>(ckv, CKVROW, kvn, KVLORA, KVLORA, kv_a_ln_w);
    rope_k_k<<<SEQ, 32>>>(ckv, kpe);
    launch_sgemm(kvn, wkv_b, kv, SEQ, KVROW, KVLORA);           // kv = kvn @ wkv_b

    // rope q (in place)
    rope_q_k<<<SEQ, 512>>>(qbuf);

    // attention
    dim3 agrid(SEQ / 64, NHEADS);
    mla_attn_k<<<agrid, 256, ATTN_SMEM>>>(qbuf, kv, kpe, attn);

    // output projection
    launch_sgemm(attn, wo, out, SEQ, HID, NHEADS * DVDIM);      // out = attn @ wo
}

// round 3
// speedup vs baseline: 1.2002x; 1.2002x over previous
#include <cuda_runtime.h>
#include <cuda_bf16.h>
#include <mma.h>
#include <math.h>
#include <stdint.h>

using namespace nvcuda;

// ---------------------------------------------------------------------------
// Problem constants
// ---------------------------------------------------------------------------
#define SEQ     2048
#define HID     2048
#define NHEADS  16
#define QLORA   1536
#define KVLORA  512
#define DROPE   64
#define DNOPE   128
#define DVDIM   128
#define QHD     192              // DNOPE + DROPE
#define QROW    (NHEADS*QHD)     // 3072
#define KVROW   (NHEADS*(DNOPE+DVDIM)) // 4096
#define CKVROW  (KVLORA+DROPE)   // 576

// ---------------------------------------------------------------------------
// Scratch (device globals; allocation-free per harness rules)
// ---------------------------------------------------------------------------
__device__ float g_qa  [SEQ*QLORA];
__device__ float g_q   [SEQ*QROW];
__device__ float g_ckv [SEQ*CKVROW];
__device__ float g_kvn [SEQ*KVLORA];
__device__ float g_kpe [SEQ*DROPE];
__device__ float g_kv  [SEQ*KVROW];
__device__ float g_attn[SEQ*HID];

__device__ __forceinline__ float to_tf32(float x) {
    uint32_t r;
    asm("cvt.rna.tf32.f32 %0, %1;" : "=r"(r) : "f"(x));
    return __uint_as_float(r);
}

// ---------------------------------------------------------------------------
// TF32 tensor-core GEMM: C[M,N] = A[M,K] * B[K,N], row-major fp32 in/out.
// 128x128x32 tile, 256 threads (8 warps, 2x4), wmma m16n16k8 tf32,
// register-prefetch double buffering.
// Requirements: M % 128 == 0, K % 32 == 0, N % 16 == 0.
// ---------------------------------------------------------------------------
#define BM 128
#define BN 128
#define BK 32
#define AS_LD (BK + 4)     // 36
#define BS_LD (BN + 4)     // 132

__global__ __launch_bounds__(256) void tgemm_k(
    const float* __restrict__ A, const float* __restrict__ B,
    float* __restrict__ C, int M, int N, int K)
{
    __shared__ float As[BM][AS_LD];   // [m][k]
    __shared__ float Bs[BK][BS_LD];   // [k][n]

    const int tid = threadIdx.x;
    const int warpId = tid >> 5;
    const int wr = warpId >> 2;        // 0..1 -> 64-row half
    const int wc = warpId & 3;         // 0..3 -> 32-col quarter
    const int br = blockIdx.y * BM;
    const int bc = blockIdx.x * BN;

    wmma::fragment<wmma::accumulator, 16, 16, 8, float> acc[4][2];
#pragma unroll
    for (int i = 0; i < 4; i++)
#pragma unroll
        for (int j = 0; j < 2; j++)
            wmma::fill_fragment(acc[i][j], 0.f);

    float4 pa[4], pb[4];

    // fetch tile k0 into registers
    auto fetch = [&](int k0) {
#pragma unroll
        for (int i = 0; i < 4; i++) {
            const int lin = i * 256 + tid;
            const int r = lin >> 3;
            const int c = (lin & 7) << 2;
            pa[i] = *reinterpret_cast<const float4*>(
                &A[(size_t)(br + r) * K + k0 + c]);
        }
#pragma unroll
        for (int i = 0; i < 4; i++) {
            const int lin = i * 256 + tid;
            const int r = lin >> 5;
            const int c = (lin & 31) << 2;
            const int gc = bc + c;
            float4 v = make_float4(0.f, 0.f, 0.f, 0.f);
            if (gc < N)
                v = *reinterpret_cast<const float4*>(
                    &B[(size_t)(k0 + r) * N + gc]);
            pb[i] = v;
        }
    };

    // commit registers -> smem (with tf32 rounding)
    auto commit = [&]() {
#pragma unroll
        for (int i = 0; i < 4; i++) {
            const int lin = i * 256 + tid;
            const int r = lin >> 3;
            const int c = (lin & 7) << 2;
            As[r][c + 0] = to_tf32(pa[i].x);
            As[r][c + 1] = to_tf32(pa[i].y);
            As[r][c + 2] = to_tf32(pa[i].z);
            As[r][c + 3] = to_tf32(pa[i].w);
        }
#pragma unroll
        for (int i = 0; i < 4; i++) {
            const int lin = i * 256 + tid;
            const int r = lin >> 5;
            const int c = (lin & 31) << 2;
            Bs[r][c + 0] = to_tf32(pb[i].x);
            Bs[r][c + 1] = to_tf32(pb[i].y);
            Bs[r][c + 2] = to_tf32(pb[i].z);
            Bs[r][c + 3] = to_tf32(pb[i].w);
        }
    };

    fetch(0);
    commit();
    __syncthreads();

    for (int k0 = 0; k0 < K; k0 += BK) {
        const bool more = (k0 + BK) < K;
        if (more) fetch(k0 + BK);

#pragma unroll
        for (int kk = 0; kk < BK; kk += 8) {
            wmma::fragment<wmma::matrix_a, 16, 16, 8,
                           wmma::precision::tf32, wmma::row_major> af[4];
            wmma::fragment<wmma::matrix_b, 16, 16, 8,
                           wmma::precision::tf32, wmma::row_major> bf[2];
#pragma unroll
            for (int i = 0; i < 4; i++)
                wmma::load_matrix_sync(af[i], &As[wr * 64 + i * 16][kk], AS_LD);
#pragma unroll
            for (int j = 0; j < 2; j++)
                wmma::load_matrix_sync(bf[j], &Bs[kk][wc * 32 + j * 16], BS_LD);
#pragma unroll
            for (int i = 0; i < 4; i++)
#pragma unroll
                for (int j = 0; j < 2; j++)
                    wmma::mma_sync(acc[i][j], af[i], bf[j], acc[i][j]);
        }
        __syncthreads();
        if (more) {
            commit();
            __syncthreads();
        }
    }

#pragma unroll
    for (int i = 0; i < 4; i++) {
        const int gr = br + wr * 64 + i * 16;
#pragma unroll
        for (int j = 0; j < 2; j++) {
            const int gc = bc + wc * 32 + j * 16;
            if (gc < N)
                wmma::store_matrix_sync(&C[(size_t)gr * N + gc], acc[i][j],
                                        N, wmma::mem_row_major);
        }
    }
}

// ---------------------------------------------------------------------------
// RMSNorm: one block per row.
// ---------------------------------------------------------------------------
__global__ __launch_bounds__(256) void rmsnorm_k(
    const float* __restrict__ in, int istride,
    float* __restrict__ out, int ostride,
    int dim, const float* __restrict__ w)
{
    const int row = blockIdx.x;
    const float* x = in + (size_t)row * istride;
    float* y = out + (size_t)row * ostride;

    float ss = 0.f;
    for (int i = threadIdx.x; i < dim; i += blockDim.x) {
        float v = x[i];
        ss = fmaf(v, v, ss);
    }
#pragma unroll
    for (int o = 16; o; o >>= 1) ss += __shfl_xor_sync(0xffffffffu, ss, o);

    __shared__ float red[8];
    if ((threadIdx.x & 31) == 0) red[threadIdx.x >> 5] = ss;
    __syncthreads();
    __shared__ float s_rstd;
    if (threadIdx.x == 0) {
        float v = 0.f;
        for (int i = 0; i < 8; i++) v += red[i];
        s_rstd = rsqrtf(v / (float)dim + 1e-6f);
    }
    __syncthreads();
    const float rstd = s_rstd;
    for (int i = threadIdx.x; i < dim; i += blockDim.x)
        y[i] = x[i] * rstd * w[i];
}

// ---------------------------------------------------------------------------
// RoPE on q_pe (in-place inside g_q). grid = SEQ, block = 512 (16 heads x 32)
// ---------------------------------------------------------------------------
__global__ __launch_bounds__(512) void rope_q_k(float* __restrict__ q)
{
    const int t = blockIdx.x;
    const int h = threadIdx.x >> 5;
    const int i = threadIdx.x & 31;

    const float inv = powf(10000.f, -(float)i / 32.f);
    float s, c;
    sincosf((float)t * inv, &s, &c);

    float* base = q + (size_t)t * QROW + h * QHD + DNOPE;
    const float x1 = base[i];
    const float x2 = base[i + 32];
    base[i]      = x1 * c - x2 * s;
    base[i + 32] = x2 * c + x1 * s;
}

// RoPE on k_pe: read from ckv tail, write to g_kpe. grid = SEQ, block = 32
__global__ __launch_bounds__(32) void rope_k_k(
    const float* __restrict__ ckv, float* __restrict__ kpe)
{
    const int t = blockIdx.x;
    const int i = threadIdx.x;

    const float inv = powf(10000.f, -(float)i / 32.f);
    float s, c;
    sincosf((float)t * inv, &s, &c);

    const float x1 = ckv[(size_t)t * CKVROW + KVLORA + i];
    const float x2 = ckv[(size_t)t * CKVROW + KVLORA + 32 + i];
    kpe[(size_t)t * DROPE + i]      = x1 * c - x2 * s;
    kpe[(size_t)t * DROPE + 32 + i] = x2 * c + x1 * s;
}

// ---------------------------------------------------------------------------
// Flash attention (causal), fp32 SIMT.
// grid = (SEQ/64, NHEADS), block = 256 (16x16 thread grid).
// ---------------------------------------------------------------------------
#define QS_STRIDE 196
#define KS_STRIDE 196
#define VS_STRIDE 132
#define PS_STRIDE 68
#define ATTN_SMEM ((64*QS_STRIDE + 64*KS_STRIDE + 64*VS_STRIDE + 64*PS_STRIDE) * 4)

__global__ __launch_bounds__(256) void mla_attn_k(
    const float* __restrict__ q, const float* __restrict__ kv,
    const float* __restrict__ kpe, float* __restrict__ out)
{
    extern __shared__ float sm[];
    float* Qs = sm;
    float* Ks = Qs + 64 * QS_STRIDE;
    float* Vs = Ks + 64 * KS_STRIDE;
    float* Ps = Vs + 64 * VS_STRIDE;

    const int h  = blockIdx.y;
    const int qb = blockIdx.x;
    const int tid = threadIdx.x;
    const int tx = tid & 15;
    const int ty = tid >> 4;

    const float scale = rsqrtf((float)QHD);

    for (int idx = tid; idx < 64 * QHD; idx += 256) {
        const int r = idx / QHD, d = idx % QHD;
        Qs[r * QS_STRIDE + d] =
            q[(size_t)(qb * 64 + r) * QROW + h * QHD + d] * scale;
    }

    float m[4], l[4], O[4][8];
#pragma unroll
    for (int i = 0; i < 4; i++) {
        m[i] = -INFINITY; l[i] = 0.f;
#pragma unroll
        for (int c = 0; c < 8; c++) O[i][c] = 0.f;
    }
    __syncthreads();

    for (int kb = 0; kb <= qb; kb++) {
        for (int idx = tid; idx < 64 * QHD; idx += 256) {
            const int r = idx / QHD, d = idx % QHD;
            const int cgl = kb * 64 + r;
            Ks[r * KS_STRIDE + d] = (d < DNOPE)
                ? kv[(size_t)cgl * KVROW + h * 256 + d]
                : kpe[(size_t)cgl * DROPE + (d - DNOPE)];
        }
        for (int idx = tid; idx < 64 * DVDIM; idx += 256) {
            const int r = idx >> 7, d = idx & 127;
            const int cgl = kb * 64 + r;
            Vs[r * VS_STRIDE + d] = kv[(size_t)cgl * KVROW + h * 256 + DNOPE + d];
        }
        __syncthreads();

        float S[4][4];
#pragma unroll
        for (int i = 0; i < 4; i++)
#pragma unroll
            for (int j = 0; j < 4; j++) S[i][j] = 0.f;

        for (int d = 0; d < QHD; d += 4) {
            float4 a[4], b[4];
#pragma unroll
            for (int i = 0; i < 4; i++)
                a[i] = *reinterpret_cast<const float4*>(&Qs[(ty * 4 + i) * QS_STRIDE + d]);
#pragma unroll
            for (int j = 0; j < 4; j++)
                b[j] = *reinterpret_cast<const float4*>(&Ks[(tx * 4 + j) * KS_STRIDE + d]);
#pragma unroll
            for (int i = 0; i < 4; i++)
#pragma unroll
                for (int j = 0; j < 4; j++) {
                    S[i][j] = fmaf(a[i].x, b[j].x, S[i][j]);
                    S[i][j] = fmaf(a[i].y, b[j].y, S[i][j]);
                    S[i][j] = fmaf(a[i].z, b[j].z, S[i][j]);
                    S[i][j] = fmaf(a[i].w, b[j].w, S[i][j]);
                }
        }

        if (kb == qb) {
            const int gr0 = qb * 64 + ty * 4;
            const int gc0 = kb * 64 + tx * 4;
#pragma unroll
            for (int i = 0; i < 4; i++)
#pragma unroll
                for (int j = 0; j < 4; j++)
                    if (gc0 + j > gr0 + i) S[i][j] = -INFINITY;
        }

        float f[4];
#pragma unroll
        for (int i = 0; i < 4; i++) {
            float v = S[i][0];
            v = fmaxf(v, S[i][1]); v = fmaxf(v, S[i][2]); v = fmaxf(v, S[i][3]);
#pragma unroll
            for (int o = 8; o; o >>= 1) v = fmaxf(v, __shfl_xor_sync(0xffffffffu, v, o));
            const float mnew = fmaxf(m[i], v);
            f[i] = __expf(m[i] - mnew);
            m[i] = mnew;
        }
#pragma unroll
        for (int i = 0; i < 4; i++) {
            float lloc = 0.f;
#pragma unroll
            for (int j = 0; j < 4; j++) {
                const float p = __expf(S[i][j] - m[i]);
                Ps[(ty * 4 + i) * PS_STRIDE + tx * 4 + j] = p;
                lloc += p;
            }
#pragma unroll
            for (int o = 8; o; o >>= 1) lloc += __shfl_xor_sync(0xffffffffu, lloc, o);
            l[i] = l[i] * f[i] + lloc;
        }
#pragma unroll
        for (int i = 0; i < 4; i++)
#pragma unroll
            for (int c = 0; c < 8; c++) O[i][c] *= f[i];
        __syncthreads();

        for (int j = 0; j < 64; j++) {
            float p[4];
#pragma unroll
            for (int i = 0; i < 4; i++) p[i] = Ps[(ty * 4 + i) * PS_STRIDE + j];
            const float4 v0 = *reinterpret_cast<const float4*>(&Vs[j * VS_STRIDE + tx * 8]);
            const float4 v1 = *reinterpret_cast<const float4*>(&Vs[j * VS_STRIDE + tx * 8 + 4]);
#pragma unroll
            for (int i = 0; i < 4; i++) {
                O[i][0] = fmaf(p[i], v0.x, O[i][0]);
                O[i][1] = fmaf(p[i], v0.y, O[i][1]);
                O[i][2] = fmaf(p[i], v0.z, O[i][2]);
                O[i][3] = fmaf(p[i], v0.w, O[i][3]);
                O[i][4] = fmaf(p[i], v1.x, O[i][4]);
                O[i][5] = fmaf(p[i], v1.y, O[i][5]);
                O[i][6] = fmaf(p[i], v1.z, O[i][6]);
                O[i][7] = fmaf(p[i], v1.w, O[i][7]);
            }
        }
        __syncthreads();
    }

#pragma unroll
    for (int i = 0; i < 4; i++) {
        const float inv = 1.f / l[i];
        const int row = qb * 64 + ty * 4 + i;
#pragma unroll
        for (int c = 0; c < 8; c++)
            out[(size_t)row * HID + h * DVDIM + tx * 8 + c] = O[i][c] * inv;
    }
}

// ---------------------------------------------------------------------------
// Launch
// ---------------------------------------------------------------------------
static inline void launch_tgemm(const float* A, const float* B, float* C,
                                int M, int N, int K)
{
    dim3 grid((N + BN - 1) / BN, M / BM);
    tgemm_k<<<grid, 256>>>(A, B, C, M, N, K);
}

extern "C" void kernel_launch(void* const* d_in, const int* in_sizes, int n_in,
                              void* d_out, int out_size)
{
    const float* x        = (const float*)d_in[0];
    const float* wq_a     = (const float*)d_in[1];
    const float* q_a_ln_w = (const float*)d_in[2];
    const float* wq_b     = (const float*)d_in[3];
    const float* wkv_a    = (const float*)d_in[4];
    const float* kv_a_ln_w= (const float*)d_in[5];
    const float* wkv_b    = (const float*)d_in[6];
    const float* wo       = (const float*)d_in[7];
    float* out            = (float*)d_out;

    float *qa, *qbuf, *ckv, *kvn, *kpe, *kv, *attn;
    cudaGetSymbolAddress((void**)&qa,   g_qa);
    cudaGetSymbolAddress((void**)&qbuf, g_q);
    cudaGetSymbolAddress((void**)&ckv,  g_ckv);
    cudaGetSymbolAddress((void**)&kvn,  g_kvn);
    cudaGetSymbolAddress((void**)&kpe,  g_kpe);
    cudaGetSymbolAddress((void**)&kv,   g_kv);
    cudaGetSymbolAddress((void**)&attn, g_attn);

    cudaFuncSetAttribute(mla_attn_k,
        cudaFuncAttributeMaxDynamicSharedMemorySize, ATTN_SMEM);

    // q path
    launch_tgemm(x, wq_a, qa, SEQ, QLORA, HID);
    rmsnorm_k<<<SEQ, 256>>>(qa, QLORA, qa, QLORA, QLORA, q_a_ln_w);
    launch_tgemm(qa, wq_b, qbuf, SEQ, QROW, QLORA);

    // kv path
    launch_tgemm(x, wkv_a, ckv, SEQ, CKVROW, HID);
    rmsnorm_k<<<SEQ, 256>>>(ckv, CKVROW, kvn, KVLORA, KVLORA, kv_a_ln_w);
    rope_k_k<<<SEQ, 32>>>(ckv, kpe);
    launch_tgemm(kvn, wkv_b, kv, SEQ, KVROW, KVLORA);

    // rope q (in place)
    rope_q_k<<<SEQ, 512>>>(qbuf);

    // attention
    dim3 agrid(SEQ / 64, NHEADS);
    mla_attn_k<<<agrid, 256, ATTN_SMEM>>>(qbuf, kv, kpe, attn);

    // output projection
    launch_tgemm(attn, wo, out, SEQ, HID, NHEADS * DVDIM);
}

// round 4
// speedup vs baseline: 1.6316x; 1.3595x over previous
#include <cuda_runtime.h>
#include <cuda_bf16.h>
#include <mma.h>
#include <math.h>
#include <stdint.h>

using namespace nvcuda;

// ---------------------------------------------------------------------------
// Problem constants
// ---------------------------------------------------------------------------
#define SEQ     2048
#define HID     2048
#define NHEADS  16
#define QLORA   1536
#define KVLORA  512
#define DROPE   64
#define DNOPE   128
#define DVDIM   128
#define QHD     192
#define QROW    (NHEADS*QHD)            // 3072
#define KVROW   (NHEADS*(DNOPE+DVDIM))  // 4096
#define CKVROW  (KVLORA+DROPE)          // 576

// ---------------------------------------------------------------------------
// Scratch (device globals)
// ---------------------------------------------------------------------------
__device__ float g_qa  [SEQ*QLORA];
__device__ float g_q   [SEQ*QROW];
__device__ float g_ckv [SEQ*CKVROW];
__device__ float g_kvn [SEQ*KVLORA];
__device__ float g_kpe [SEQ*DROPE];
__device__ float g_kv  [SEQ*KVROW];
__device__ float g_attn[SEQ*HID];
// tf32-rounded copies of GEMM inputs
__device__ float g_rx   [SEQ*HID];
__device__ float g_rwqa [HID*QLORA];
__device__ float g_rwqb [QLORA*QROW];
__device__ float g_rwkva[HID*CKVROW];
__device__ float g_rwkvb[KVLORA*KVROW];
__device__ float g_rwo  [HID*HID];

__device__ __forceinline__ float rna(float x) {
    uint32_t r;
    asm("cvt.rna.tf32.f32 %0, %1;" : "=r"(r) : "f"(x));
    return __uint_as_float(r);
}

// ---------------------------------------------------------------------------
// elementwise tf32 round copy (float4)
// ---------------------------------------------------------------------------
__global__ __launch_bounds__(256) void round_copy_k(
    const float4* __restrict__ in, float4* __restrict__ out, int n4)
{
    int i = blockIdx.x * 256 + threadIdx.x;
    if (i < n4) {
        float4 v = in[i];
        v.x = rna(v.x); v.y = rna(v.y); v.z = rna(v.z); v.w = rna(v.w);
        out[i] = v;
    }
}

// ---------------------------------------------------------------------------
// TF32 wmma GEMM with cp.async 2-stage pipeline.
// C[M,N] = A[M,K]*B[K,N], A/B pre-rounded to tf32 values.
// M%128==0, K%32==0, N%16==0, N%4==0.
// ---------------------------------------------------------------------------
#define BM 128
#define BN 128
#define BK 32
#define AS_LD 36
#define BS_LD 132
#define STAGE_F (BM*AS_LD + BK*BS_LD)   // 8832 floats
#define GEMM_SMEM (2*STAGE_F*4)         // 70656 B

__global__ __launch_bounds__(256, 2) void tgemm_k(
    const float* __restrict__ A, const float* __restrict__ B,
    float* __restrict__ C, int M, int N, int K)
{
    extern __shared__ float smem[];
    const int tid = threadIdx.x;
    const int warpId = tid >> 5;
    const int wr = warpId >> 2;
    const int wc = warpId & 3;
    const int br = blockIdx.y * BM;
    const int bc = blockIdx.x * BN;

    float* Asb[2] = { smem,              smem + STAGE_F };
    float* Bsb[2] = { smem + BM*AS_LD,   smem + STAGE_F + BM*AS_LD };

    wmma::fragment<wmma::accumulator, 16, 16, 8, float> acc[4][2];
#pragma unroll
    for (int i = 0; i < 4; i++)
#pragma unroll
        for (int j = 0; j < 2; j++)
            wmma::fill_fragment(acc[i][j], 0.f);

    auto issue = [&](int k0, int st) {
#pragma unroll
        for (int i = 0; i < 4; i++) {
            const int lin = i * 256 + tid;
            const int r = lin >> 3, c = (lin & 7) << 2;
            uint32_t dst = (uint32_t)__cvta_generic_to_shared(&Asb[st][r*AS_LD + c]);
            const float* src = &A[(size_t)(br + r) * K + k0 + c];
            asm volatile("cp.async.cg.shared.global [%0], [%1], 16;\n"
                         :: "r"(dst), "l"(src));
        }
#pragma unroll
        for (int i = 0; i < 4; i++) {
            const int lin = i * 256 + tid;
            const int r = lin >> 5, c = (lin & 31) << 2;
            const int gc = bc + c;
            uint32_t dst = (uint32_t)__cvta_generic_to_shared(&Bsb[st][r*BS_LD + c]);
            const float* src = &B[(size_t)(k0 + r) * N + gc];
            const int sz = (gc < N) ? 16 : 0;
            asm volatile("cp.async.cg.shared.global [%0], [%1], 16, %2;\n"
                         :: "r"(dst), "l"(src), "r"(sz));
        }
        asm volatile("cp.async.commit_group;\n");
    };

    issue(0, 0);
    const int nsteps = K / BK;

    for (int s = 0; s < nsteps; s++) {
        asm volatile("cp.async.wait_group 0;\n");
        __syncthreads();
        if (s + 1 < nsteps) issue((s + 1) * BK, (s + 1) & 1);

        const float* As = Asb[s & 1];
        const float* Bs = Bsb[s & 1];
#pragma unroll
        for (int kk = 0; kk < BK; kk += 8) {
            wmma::fragment<wmma::matrix_a, 16, 16, 8,
                           wmma::precision::tf32, wmma::row_major> af[4];
            wmma::fragment<wmma::matrix_b, 16, 16, 8,
                           wmma::precision::tf32, wmma::row_major> bf[2];
#pragma unroll
            for (int i = 0; i < 4; i++)
                wmma::load_matrix_sync(af[i], &As[(wr*64 + i*16)*AS_LD + kk], AS_LD);
#pragma unroll
            for (int j = 0; j < 2; j++)
                wmma::load_matrix_sync(bf[j], &Bs[kk*BS_LD + wc*32 + j*16], BS_LD);
#pragma unroll
            for (int i = 0; i < 4; i++)
#pragma unroll
                for (int j = 0; j < 2; j++)
                    wmma::mma_sync(acc[i][j], af[i], bf[j], acc[i][j]);
        }
        __syncthreads();
    }

#pragma unroll
    for (int i = 0; i < 4; i++) {
        const int gr = br + wr*64 + i*16;
#pragma unroll
        for (int j = 0; j < 2; j++) {
            const int gc = bc + wc*32 + j*16;
            if (gc < N)
                wmma::store_matrix_sync(&C[(size_t)gr * N + gc], acc[i][j],
                                        N, wmma::mem_row_major);
        }
    }
}

// ---------------------------------------------------------------------------
// RMSNorm (output tf32-rounded: feeds a GEMM)
// ---------------------------------------------------------------------------
__global__ __launch_bounds__(256) void rmsnorm_k(
    const float* __restrict__ in, int istride,
    float* __restrict__ out, int ostride,
    int dim, const float* __restrict__ w)
{
    const int row = blockIdx.x;
    const float* x = in + (size_t)row * istride;
    float* y = out + (size_t)row * ostride;

    float ss = 0.f;
    for (int i = threadIdx.x; i < dim; i += blockDim.x) {
        float v = x[i];
        ss = fmaf(v, v, ss);
    }
#pragma unroll
    for (int o = 16; o; o >>= 1) ss += __shfl_xor_sync(0xffffffffu, ss, o);

    __shared__ float red[8];
    if ((threadIdx.x & 31) == 0) red[threadIdx.x >> 5] = ss;
    __syncthreads();
    __shared__ float s_rstd;
    if (threadIdx.x == 0) {
        float v = 0.f;
        for (int i = 0; i < 8; i++) v += red[i];
        s_rstd = rsqrtf(v / (float)dim + 1e-6f);
    }
    __syncthreads();
    const float rstd = s_rstd;
    for (int i = threadIdx.x; i < dim; i += blockDim.x)
        y[i] = rna(x[i] * rstd * w[i]);
}

// ---------------------------------------------------------------------------
// RoPE kernels
// ---------------------------------------------------------------------------
__global__ __launch_bounds__(512) void rope_q_k(float* __restrict__ q)
{
    const int t = blockIdx.x;
    const int h = threadIdx.x >> 5;
    const int i = threadIdx.x & 31;
    const float inv = powf(10000.f, -(float)i / 32.f);
    float s, c;
    sincosf((float)t * inv, &s, &c);
    float* base = q + (size_t)t * QROW + h * QHD + DNOPE;
    const float x1 = base[i];
    const float x2 = base[i + 32];
    base[i]      = x1 * c - x2 * s;
    base[i + 32] = x2 * c + x1 * s;
}

__global__ __launch_bounds__(32) void rope_k_k(
    const float* __restrict__ ckv, float* __restrict__ kpe)
{
    const int t = blockIdx.x;
    const int i = threadIdx.x;
    const float inv = powf(10000.f, -(float)i / 32.f);
    float s, c;
    sincosf((float)t * inv, &s, &c);
    const float x1 = ckv[(size_t)t * CKVROW + KVLORA + i];
    const float x2 = ckv[(size_t)t * CKVROW + KVLORA + 32 + i];
    kpe[(size_t)t * DROPE + i]      = x1 * c - x2 * s;
    kpe[(size_t)t * DROPE + 32 + i] = x2 * c + x1 * s;
}

// ---------------------------------------------------------------------------
// Tensor-core flash attention (causal), tf32 mma.m16n8k8 with split precision:
//   S  = (Qhi + Qlo) * K        (2 passes)
//   O += Phi*Vhi + Plo*Vhi + Phi*Vlo   (3 passes)
// grid=(32,16), block=256 (8 warps). q-tile 64 rows, k-tile 64, d in 3x64.
// ---------------------------------------------------------------------------
#define QS 196
#define KS_S 68
#define VS_S 132
#define PS_S 68

// float offsets in dynamic smem
#define OFF_QHI 0
#define OFF_QLO (OFF_QHI + 64*QS)
#define OFF_KS  (OFF_QLO + 64*QS)
#define OFF_VHI (OFF_KS  + 64*KS_S)
#define OFF_VLO (OFF_VHI + 64*VS_S)
#define OFF_PHI (OFF_VLO + 64*VS_S)
#define OFF_PLO (OFF_PHI + 64*PS_S)
#define OFF_M   (OFF_PLO + 64*PS_S)
#define OFF_L   (OFF_M + 64)
#define OFF_F   (OFF_L + 64)
#define OFF_RM  (OFF_F + 64)
#define OFF_RS  (OFF_RM + 64*4)
#define ATTN_F  (OFF_RS + 64*4)
#define ATTN_SMEM (ATTN_F*4)

__device__ __forceinline__ void mma8(float* d,
    uint32_t a0, uint32_t a1, uint32_t a2, uint32_t a3,
    uint32_t b0, uint32_t b1)
{
    asm volatile(
        "mma.sync.aligned.m16n8k8.row.col.f32.tf32.tf32.f32 "
        "{%0,%1,%2,%3}, {%4,%5,%6,%7}, {%8,%9}, {%0,%1,%2,%3};\n"
        : "+f"(d[0]), "+f"(d[1]), "+f"(d[2]), "+f"(d[3])
        : "r"(a0), "r"(a1), "r"(a2), "r"(a3), "r"(b0), "r"(b1));
}

__device__ __forceinline__ uint32_t f2u(float x) { return __float_as_uint(x); }

__global__ __launch_bounds__(256) void mla_attn_tc(
    const float* __restrict__ q, const float* __restrict__ kv,
    const float* __restrict__ kpe, float* __restrict__ out)
{
    extern __shared__ float sm[];
    float* Qhi = sm + OFF_QHI;
    float* Qlo = sm + OFF_QLO;
    float* Ks  = sm + OFF_KS;
    float* Vhi = sm + OFF_VHI;
    float* Vlo = sm + OFF_VLO;
    float* Phi = sm + OFF_PHI;
    float* Plo = sm + OFF_PLO;
    float* smM = sm + OFF_M;
    float* smL = sm + OFF_L;
    float* smF = sm + OFF_F;
    float* redM = sm + OFF_RM;
    float* redS = sm + OFF_RS;

    const int h  = blockIdx.y;
    const int qb = gridDim.x - 1 - blockIdx.x;   // heavy tiles first
    const int tid = threadIdx.x;
    const int wid = tid >> 5;
    const int lane = tid & 31;
    const int wr = wid >> 2;      // 0..1
    const int wc = wid & 3;       // 0..3
    const int lq = lane >> 2;     // 0..7
    const int lr = lane & 3;      // 0..3

    const float scale = rsqrtf(192.f);

    // stage Q (hi/lo split of scaled values)
    for (int idx = tid; idx < 64*192; idx += 256) {
        const int r = idx / 192, d = idx % 192;
        const float v = q[(size_t)(qb*64 + r) * QROW + h*QHD + d] * scale;
        const float hi = rna(v);
        Qhi[r*QS + d] = hi;
        Qlo[r*QS + d] = rna(v - hi);
    }
    if (tid < 64) { smM[tid] = -INFINITY; smL[tid] = 0.f; }

    float Oacc[2][4][4];
#pragma unroll
    for (int mt = 0; mt < 2; mt++)
#pragma unroll
        for (int nt = 0; nt < 4; nt++)
#pragma unroll
            for (int i = 0; i < 4; i++) Oacc[mt][nt][i] = 0.f;

    for (int kb = 0; kb <= qb; kb++) {
        float Sacc[2][2][4];
#pragma unroll
        for (int mt = 0; mt < 2; mt++)
#pragma unroll
            for (int nt = 0; nt < 2; nt++)
#pragma unroll
                for (int i = 0; i < 4; i++) Sacc[mt][nt][i] = 0.f;

        // ---- S = Q K^T over 3 d-chunks of 64
#pragma unroll 1
        for (int c = 0; c < 3; c++) {
            __syncthreads();
            for (int idx = tid; idx < 64*64; idx += 256) {
                const int r = idx >> 6, d = idx & 63;
                const int gd = c*64 + d;
                const float v = (gd < DNOPE)
                    ? kv[(size_t)(kb*64 + r) * KVROW + h*256 + gd]
                    : kpe[(size_t)(kb*64 + r) * DROPE + gd - DNOPE];
                Ks[r*KS_S + d] = rna(v);
            }
            __syncthreads();

#pragma unroll
            for (int ks = 0; ks < 8; ks++) {
                const int kof = ks*8 + lr;
                uint32_t b[2][2];
#pragma unroll
                for (int nt = 0; nt < 2; nt++) {
                    const int n = wc*16 + nt*8 + lq;
                    b[nt][0] = f2u(Ks[n*KS_S + kof]);
                    b[nt][1] = f2u(Ks[n*KS_S + kof + 4]);
                }
#pragma unroll
                for (int pass = 0; pass < 2; pass++) {
                    const float* Qp = pass ? Qlo : Qhi;
#pragma unroll
                    for (int mt = 0; mt < 2; mt++) {
                        const int r0 = wr*32 + mt*16 + lq;
                        const int colb = c*64 + kof;
                        uint32_t a0 = f2u(Qp[r0*QS + colb]);
                        uint32_t a1 = f2u(Qp[(r0+8)*QS + colb]);
                        uint32_t a2 = f2u(Qp[r0*QS + colb + 4]);
                        uint32_t a3 = f2u(Qp[(r0+8)*QS + colb + 4]);
#pragma unroll
                        for (int nt = 0; nt < 2; nt++)
                            mma8(Sacc[mt][nt], a0, a1, a2, a3, b[nt][0], b[nt][1]);
                    }
                }
            }
        }

        // ---- stage V (hi/lo). Safe: prior PV finished (chunk-loop syncs).
        for (int idx = tid; idx < 64*128; idx += 256) {
            const int r = idx >> 7, d = idx & 127;
            const float v = kv[(size_t)(kb*64 + r) * KVROW + h*256 + DNOPE + d];
            const float hi = rna(v);
            Vhi[r*VS_S + d] = hi;
            Vlo[r*VS_S + d] = rna(v - hi);
        }

        // ---- softmax: mask + per-thread row maxima
        float tmax[2][2] = { {-INFINITY,-INFINITY}, {-INFINITY,-INFINITY} };
#pragma unroll
        for (int mt = 0; mt < 2; mt++)
#pragma unroll
            for (int nt = 0; nt < 2; nt++)
#pragma unroll
                for (int i = 0; i < 4; i++) {
                    if (kb == qb) {
                        const int row = wr*32 + mt*16 + lq + (i >> 1)*8;
                        const int col = wc*16 + nt*8 + lr*2 + (i & 1);
                        if (col > row) Sacc[mt][nt][i] = -INFINITY;
                    }
                    tmax[mt][i>>1] = fmaxf(tmax[mt][i>>1], Sacc[mt][nt][i]);
                }
#pragma unroll
        for (int mt = 0; mt < 2; mt++)
#pragma unroll
            for (int u = 0; u < 2; u++) {
                float v = tmax[mt][u];
                v = fmaxf(v, __shfl_xor_sync(0xffffffffu, v, 1));
                v = fmaxf(v, __shfl_xor_sync(0xffffffffu, v, 2));
                tmax[mt][u] = v;
            }
        if (lr == 0) {
#pragma unroll
            for (int mt = 0; mt < 2; mt++)
#pragma unroll
                for (int u = 0; u < 2; u++)
                    redM[(wr*32 + mt*16 + lq + u*8)*4 + wc] = tmax[mt][u];
        }
        __syncthreads();

        if (wc == 0 && lr == 0) {
#pragma unroll
            for (int mt = 0; mt < 2; mt++)
#pragma unroll
                for (int u = 0; u < 2; u++) {
                    const int row = wr*32 + mt*16 + lq + u*8;
                    float mx = fmaxf(fmaxf(redM[row*4+0], redM[row*4+1]),
                                     fmaxf(redM[row*4+2], redM[row*4+3]));
                    const float mo = smM[row];
                    const float mn = fmaxf(mo, mx);
                    smM[row] = mn;
                    smF[row] = __expf(mo - mn);
                }
        }
        __syncthreads();

        // p = exp(s - m), hi/lo split into Phi/Plo, partial sums; rescale O
        float mn[2][2];
#pragma unroll
        for (int mt = 0; mt < 2; mt++)
#pragma unroll
            for (int u = 0; u < 2; u++)
                mn[mt][u] = smM[wr*32 + mt*16 + lq + u*8];

        float tsum[2][2] = { {0.f,0.f}, {0.f,0.f} };
#pragma unroll
        for (int mt = 0; mt < 2; mt++)
#pragma unroll
            for (int nt = 0; nt < 2; nt++)
#pragma unroll
                for (int i = 0; i < 4; i++) {
                    const int u = i >> 1;
                    const float p = __expf(Sacc[mt][nt][i] - mn[mt][u]);
                    const int row = wr*32 + mt*16 + lq + u*8;
                    const int col = wc*16 + nt*8 + lr*2 + (i & 1);
                    const float phi = rna(p);
                    Phi[row*PS_S + col] = phi;
                    Plo[row*PS_S + col] = rna(p - phi);
                    tsum[mt][u] += p;
                }
#pragma unroll
        for (int mt = 0; mt < 2; mt++)
#pragma unroll
            for (int u = 0; u < 2; u++) {
                float v = tsum[mt][u];
                v += __shfl_xor_sync(0xffffffffu, v, 1);
                v += __shfl_xor_sync(0xffffffffu, v, 2);
                tsum[mt][u] = v;
            }
        if (lr == 0) {
#pragma unroll
            for (int mt = 0; mt < 2; mt++)
#pragma unroll
                for (int u = 0; u < 2; u++)
                    redS[(wr*32 + mt*16 + lq + u*8)*4 + wc] = tsum[mt][u];
        }
        // rescale O accumulators by f
#pragma unroll
        for (int mt = 0; mt < 2; mt++) {
            const int r0 = wr*32 + mt*16 + lq;
            const float f0 = smF[r0], f1 = smF[r0 + 8];
#pragma unroll
            for (int nt = 0; nt < 4; nt++) {
                Oacc[mt][nt][0] *= f0; Oacc[mt][nt][1] *= f0;
                Oacc[mt][nt][2] *= f1; Oacc[mt][nt][3] *= f1;
            }
        }
        __syncthreads();

        if (wc == 0 && lr == 0) {
#pragma unroll
            for (int mt = 0; mt < 2; mt++)
#pragma unroll
                for (int u = 0; u < 2; u++) {
                    const int row = wr*32 + mt*16 + lq + u*8;
                    smL[row] = smL[row]*smF[row] +
                        (redS[row*4+0] + redS[row*4+1] + redS[row*4+2] + redS[row*4+3]);
                }
        }

        // ---- O += P V (3 passes)
#pragma unroll
        for (int ks = 0; ks < 8; ks++) {
            const int k0 = ks*8 + lr;
            uint32_t bh[4][2], bl[4][2];
#pragma unroll
            for (int nt = 0; nt < 4; nt++) {
                const int n = wc*32 + nt*8 + lq;
                bh[nt][0] = f2u(Vhi[k0*VS_S + n]);
                bh[nt][1] = f2u(Vhi[(k0+4)*VS_S + n]);
                bl[nt][0] = f2u(Vlo[k0*VS_S + n]);
                bl[nt][1] = f2u(Vlo[(k0+4)*VS_S + n]);
            }
#pragma unroll
            for (int mt = 0; mt < 2; mt++) {
                const int r0 = wr*32 + mt*16 + lq;
                uint32_t ah0 = f2u(Phi[r0*PS_S + k0]);
                uint32_t ah1 = f2u(Phi[(r0+8)*PS_S + k0]);
                uint32_t ah2 = f2u(Phi[r0*PS_S + k0 + 4]);
                uint32_t ah3 = f2u(Phi[(r0+8)*PS_S + k0 + 4]);
                uint32_t al0 = f2u(Plo[r0*PS_S + k0]);
                uint32_t al1 = f2u(Plo[(r0+8)*PS_S + k0]);
                uint32_t al2 = f2u(Plo[r0*PS_S + k0 + 4]);
                uint32_t al3 = f2u(Plo[(r0+8)*PS_S + k0 + 4]);
#pragma unroll
                for (int nt = 0; nt < 4; nt++) {
                    mma8(Oacc[mt][nt], ah0, ah1, ah2, ah3, bh[nt][0], bh[nt][1]);
                    mma8(Oacc[mt][nt], al0, al1, al2, al3, bh[nt][0], bh[nt][1]);
                    mma8(Oacc[mt][nt], ah0, ah1, ah2, ah3, bl[nt][0], bl[nt][1]);
                }
            }
        }
    }

    __syncthreads();   // smL final

    // epilogue: O/l, tf32-round (feeds wo GEMM), store
#pragma unroll
    for (int mt = 0; mt < 2; mt++) {
        const int r0 = wr*32 + mt*16 + lq;
        const float inv0 = 1.f / smL[r0];
        const float inv1 = 1.f / smL[r0 + 8];
#pragma unroll
        for (int nt = 0; nt < 4; nt++) {
#pragma unroll
            for (int i = 0; i < 4; i++) {
                const int row = (i < 2) ? r0 : (r0 + 8);
                const int col = wc*32 + nt*8 + lr*2 + (i & 1);
                out[(size_t)(qb*64 + row) * HID + h*DVDIM + col] =
                    rna(Oacc[mt][nt][i] * ((i < 2) ? inv0 : inv1));
            }
        }
    }
}

// ---------------------------------------------------------------------------
// Launch
// ---------------------------------------------------------------------------
static inline void launch_tgemm(const float* A, const float* B, float* C,
                                int M, int N, int K)
{
    dim3 grid((N + BN - 1) / BN, M / BM);
    tgemm_k<<<grid, 256, GEMM_SMEM>>>(A, B, C, M, N, K);
}

static inline void launch_round(const float* in, float* out, int n)
{
    const int n4 = n / 4;
    round_copy_k<<<(n4 + 255) / 256, 256>>>(
        (const float4*)in, (float4*)out, n4);
}

extern "C" void kernel_launch(void* const* d_in, const int* in_sizes, int n_in,
                              void* d_out, int out_size)
{
    const float* x        = (const float*)d_in[0];
    const float* wq_a     = (const float*)d_in[1];
    const float* q_a_ln_w = (const float*)d_in[2];
    const float* wq_b     = (const float*)d_in[3];
    const float* wkv_a    = (const float*)d_in[4];
    const float* kv_a_ln_w= (const float*)d_in[5];
    const float* wkv_b    = (const float*)d_in[6];
    const float* wo       = (const float*)d_in[7];
    float* out            = (float*)d_out;

    float *qa, *qbuf, *ckv, *kvn, *kpe, *kv, *attn;
    float *rx, *rwqa, *rwqb, *rwkva, *rwkvb, *rwo;
    cudaGetSymbolAddress((void**)&qa,    g_qa);
    cudaGetSymbolAddress((void**)&qbuf,  g_q);
    cudaGetSymbolAddress((void**)&ckv,   g_ckv);
    cudaGetSymbolAddress((void**)&kvn,   g_kvn);
    cudaGetSymbolAddress((void**)&kpe,   g_kpe);
    cudaGetSymbolAddress((void**)&kv,    g_kv);
    cudaGetSymbolAddress((void**)&attn,  g_attn);
    cudaGetSymbolAddress((void**)&rx,    g_rx);
    cudaGetSymbolAddress((void**)&rwqa,  g_rwqa);
    cudaGetSymbolAddress((void**)&rwqb,  g_rwqb);
    cudaGetSymbolAddress((void**)&rwkva, g_rwkva);
    cudaGetSymbolAddress((void**)&rwkvb, g_rwkvb);
    cudaGetSymbolAddress((void**)&rwo,   g_rwo);

    cudaFuncSetAttribute(tgemm_k,
        cudaFuncAttributeMaxDynamicSharedMemorySize, GEMM_SMEM);
    cudaFuncSetAttribute(mla_attn_tc,
        cudaFuncAttributeMaxDynamicSharedMemorySize, ATTN_SMEM);

    // pre-round GEMM inputs to tf32
    launch_round(x,     rx,    SEQ*HID);
    launch_round(wq_a,  rwqa,  HID*QLORA);
    launch_round(wq_b,  rwqb,  QLORA*QROW);
    launch_round(wkv_a, rwkva, HID*CKVROW);
    launch_round(wkv_b, rwkvb, KVLORA*KVROW);
    launch_round(wo,    rwo,   HID*HID);

    // q path
    launch_tgemm(rx, rwqa, qa, SEQ, QLORA, HID);
    rmsnorm_k<<<SEQ, 256>>>(qa, QLORA, qa, QLORA, QLORA, q_a_ln_w);
    launch_tgemm(qa, rwqb, qbuf, SEQ, QROW, QLORA);

    // kv path
    launch_tgemm(rx, rwkva, ckv, SEQ, CKVROW, HID);
    rmsnorm_k<<<SEQ, 256>>>(ckv, CKVROW, kvn, KVLORA, KVLORA, kv_a_ln_w);
    rope_k_k<<<SEQ, 32>>>(ckv, kpe);
    launch_tgemm(kvn, rwkvb, kv, SEQ, KVROW, KVLORA);

    // rope q (in place)
    rope_q_k<<<SEQ, 512>>>(qbuf);

    // attention (writes tf32-rounded output)
    dim3 agrid(SEQ / 64, NHEADS);
    mla_attn_tc<<<agrid, 256, ATTN_SMEM>>>(qbuf, kv, kpe, attn);

    // output projection
    launch_tgemm(attn, rwo, out, SEQ, HID, NHEADS * DVDIM);
}

// round 6
// speedup vs baseline: 1.9927x; 1.2214x over previous
#include <cuda_runtime.h>
#include <cuda_bf16.h>
#include <mma.h>
#include <math.h>
#include <stdint.h>

using namespace nvcuda;

// ---------------------------------------------------------------------------
// Problem constants
// ---------------------------------------------------------------------------
#define SEQ     2048
#define HID     2048
#define NHEADS  16
#define QLORA   1536
#define KVLORA  512
#define DROPE   64
#define DNOPE   128
#define DVDIM   128
#define QHD     192
#define QROW    (NHEADS*QHD)            // 3072
#define KVROW   (NHEADS*(DNOPE+DVDIM))  // 4096
#define CKVROW  (KVLORA+DROPE)          // 576

// ---------------------------------------------------------------------------
// Scratch (device globals)
// ---------------------------------------------------------------------------
__device__ float g_qa  [SEQ*QLORA];
__device__ float g_q   [SEQ*QROW];
__device__ float g_ckv [SEQ*CKVROW];
__device__ float g_kvn [SEQ*KVLORA];
__device__ float g_kpe [SEQ*DROPE];
__device__ float g_kv  [SEQ*KVROW];
__device__ float g_attn[SEQ*HID];
// tf32-rounded copies of GEMM inputs
__device__ float g_rx   [SEQ*HID];
__device__ float g_rwqa [HID*QLORA];
__device__ float g_rwqb [QLORA*QROW];
__device__ float g_rwkva[HID*CKVROW];
__device__ float g_rwkvb[KVLORA*KVROW];
__device__ float g_rwo  [HID*HID];

__device__ __forceinline__ float rna(float x) {
    uint32_t r;
    asm("cvt.rna.tf32.f32 %0, %1;" : "=r"(r) : "f"(x));
    return __uint_as_float(r);
}

// ---------------------------------------------------------------------------
// elementwise tf32 round copy (float4)
// ---------------------------------------------------------------------------
__global__ __launch_bounds__(256) void round_copy_k(
    const float4* __restrict__ in, float4* __restrict__ out, int n4)
{
    int i = blockIdx.x * 256 + threadIdx.x;
    if (i < n4) {
        float4 v = in[i];
        v.x = rna(v.x); v.y = rna(v.y); v.z = rna(v.z); v.w = rna(v.w);
        out[i] = v;
    }
}

// ---------------------------------------------------------------------------
// TF32 wmma GEMM with cp.async 3-stage pipeline.
// C[M,N] = A[M,K]*B[K,N], A/B pre-rounded to tf32 values.
// M%128==0, K%32==0, N%4==0.
// ---------------------------------------------------------------------------
#define BM 128
#define BN 128
#define BK 32
#define AS_LD 36
#define BS_LD 132
#define STAGE_F (BM*AS_LD + BK*BS_LD)   // 8832 floats
#define GEMM_SMEM (3*STAGE_F*4)         // 105984 B

__global__ __launch_bounds__(256, 2) void tgemm_k(
    const float* __restrict__ A, const float* __restrict__ B,
    float* __restrict__ C, int M, int N, int K)
{
    extern __shared__ float smem[];
    const int tid = threadIdx.x;
    const int warpId = tid >> 5;
    const int wr = warpId >> 2;
    const int wc = warpId & 3;
    const int br = blockIdx.y * BM;
    const int bc = blockIdx.x * BN;

    wmma::fragment<wmma::accumulator, 16, 16, 8, float> acc[4][2];
#pragma unroll
    for (int i = 0; i < 4; i++)
#pragma unroll
        for (int j = 0; j < 2; j++)
            wmma::fill_fragment(acc[i][j], 0.f);

    auto issue = [&](int k0, int st) {
        float* As = smem + st * STAGE_F;
        float* Bs = As + BM * AS_LD;
#pragma unroll
        for (int i = 0; i < 4; i++) {
            const int lin = i * 256 + tid;
            const int r = lin >> 3, c = (lin & 7) << 2;
            uint32_t dst = (uint32_t)__cvta_generic_to_shared(&As[r*AS_LD + c]);
            const float* src = &A[(size_t)(br + r) * K + k0 + c];
            asm volatile("cp.async.cg.shared.global [%0], [%1], 16;\n"
                         :: "r"(dst), "l"(src));
        }
#pragma unroll
        for (int i = 0; i < 4; i++) {
            const int lin = i * 256 + tid;
            const int r = lin >> 5, c = (lin & 31) << 2;
            const int gc = bc + c;
            uint32_t dst = (uint32_t)__cvta_generic_to_shared(&Bs[r*BS_LD + c]);
            const float* src = &B[(size_t)(k0 + r) * N + gc];
            const int sz = (gc < N) ? 16 : 0;
            asm volatile("cp.async.cg.shared.global [%0], [%1], 16, %2;\n"
                         :: "r"(dst), "l"(src), "r"(sz));
        }
        asm volatile("cp.async.commit_group;\n");
    };

    const int nsteps = K / BK;
    issue(0, 0);
    if (nsteps > 1) issue(BK, 1);

    for (int s = 0; s < nsteps; s++) {
        asm volatile("cp.async.wait_group 1;\n");
        __syncthreads();
        if (s + 2 < nsteps) issue((s + 2) * BK, (s + 2) % 3);

        const float* As = smem + (s % 3) * STAGE_F;
        const float* Bs = As + BM * AS_LD;
#pragma unroll
        for (int kk = 0; kk < BK; kk += 8) {
            wmma::fragment<wmma::matrix_a, 16, 16, 8,
                           wmma::precision::tf32, wmma::row_major> af[4];
            wmma::fragment<wmma::matrix_b, 16, 16, 8,
                           wmma::precision::tf32, wmma::row_major> bf[2];
#pragma unroll
            for (int i = 0; i < 4; i++)
                wmma::load_matrix_sync(af[i], &As[(wr*64 + i*16)*AS_LD + kk], AS_LD);
#pragma unroll
            for (int j = 0; j < 2; j++)
                wmma::load_matrix_sync(bf[j], &Bs[kk*BS_LD + wc*32 + j*16], BS_LD);
#pragma unroll
            for (int i = 0; i < 4; i++)
#pragma unroll
                for (int j = 0; j < 2; j++)
                    wmma::mma_sync(acc[i][j], af[i], bf[j], acc[i][j]);
        }
        __syncthreads();
    }

#pragma unroll
    for (int i = 0; i < 4; i++) {
        const int gr = br + wr*64 + i*16;
#pragma unroll
        for (int j = 0; j < 2; j++) {
            const int gc = bc + wc*32 + j*16;
            if (gc < N)
                wmma::store_matrix_sync(&C[(size_t)gr * N + gc], acc[i][j],
                                        N, wmma::mem_row_major);
        }
    }
}

// ---------------------------------------------------------------------------
// RMSNorm (output tf32-rounded: feeds a GEMM)
// ---------------------------------------------------------------------------
__global__ __launch_bounds__(256) void rmsnorm_k(
    const float* __restrict__ in, int istride,
    float* __restrict__ out, int ostride,
    int dim, const float* __restrict__ w)
{
    const int row = blockIdx.x;
    const float* x = in + (size_t)row * istride;
    float* y = out + (size_t)row * ostride;

    float ss = 0.f;
    for (int i = threadIdx.x; i < dim; i += blockDim.x) {
        float v = x[i];
        ss = fmaf(v, v, ss);
    }
#pragma unroll
    for (int o = 16; o; o >>= 1) ss += __shfl_xor_sync(0xffffffffu, ss, o);

    __shared__ float red[8];
    if ((threadIdx.x & 31) == 0) red[threadIdx.x >> 5] = ss;
    __syncthreads();
    __shared__ float s_rstd;
    if (threadIdx.x == 0) {
        float v = 0.f;
        for (int i = 0; i < 8; i++) v += red[i];
        s_rstd = rsqrtf(v / (float)dim + 1e-6f);
    }
    __syncthreads();
    const float rstd = s_rstd;
    for (int i = threadIdx.x; i < dim; i += blockDim.x)
        y[i] = rna(x[i] * rstd * w[i]);
}

// ---------------------------------------------------------------------------
// RoPE kernels
// ---------------------------------------------------------------------------
__global__ __launch_bounds__(512) void rope_q_k(float* __restrict__ q)
{
    const int t = blockIdx.x;
    const int h = threadIdx.x >> 5;
    const int i = threadIdx.x & 31;
    const float inv = powf(10000.f, -(float)i / 32.f);
    float s, c;
    sincosf((float)t * inv, &s, &c);
    float* base = q + (size_t)t * QROW + h * QHD + DNOPE;
    const float x1 = base[i];
    const float x2 = base[i + 32];
    base[i]      = x1 * c - x2 * s;
    base[i + 32] = x2 * c + x1 * s;
}

__global__ __launch_bounds__(32) void rope_k_k(
    const float* __restrict__ ckv, float* __restrict__ kpe)
{
    const int t = blockIdx.x;
    const int i = threadIdx.x;
    const float inv = powf(10000.f, -(float)i / 32.f);
    float s, c;
    sincosf((float)t * inv, &s, &c);
    const float x1 = ckv[(size_t)t * CKVROW + KVLORA + i];
    const float x2 = ckv[(size_t)t * CKVROW + KVLORA + 32 + i];
    kpe[(size_t)t * DROPE + i]      = x1 * c - x2 * s;
    kpe[(size_t)t * DROPE + 32 + i] = x2 * c + x1 * s;
}

// ---------------------------------------------------------------------------
// Tensor-core flash attention (causal), tf32 mma.m16n8k8.
// Precision: S = (Qhi+Qlo)*K ; O += Phi*Vhi + Plo*Vhi + Phi*Vlo,
// with all hi/lo splits done in REGISTERS from single fp32 smem copies.
// smem ~106KB -> 2 CTAs/SM. V processed in two 64-col chunks.
// grid=(32,16), block=256 (8 warps).
// ---------------------------------------------------------------------------
#define QS  196
#define KSS 68
#define VSS 72
#define PSS 68

#define OFF_Q  0
#define OFF_K  (OFF_Q + 64*QS)
#define OFF_V  (OFF_K + 64*KSS)
#define OFF_P  (OFF_V + 64*VSS)
#define OFF_M  (OFF_P + 64*PSS)
#define OFF_L  (OFF_M + 64)
#define OFF_F  (OFF_L + 64)
#define OFF_RM (OFF_F + 64)
#define OFF_RS (OFF_RM + 256)
#define ATTN_F (OFF_RS + 256)
#define ATTN_SMEM (ATTN_F*4)

__device__ __forceinline__ void mma8(float* d,
    uint32_t a0, uint32_t a1, uint32_t a2, uint32_t a3,
    uint32_t b0, uint32_t b1)
{
    asm volatile(
        "mma.sync.aligned.m16n8k8.row.col.f32.tf32.tf32.f32 "
        "{%0,%1,%2,%3}, {%4,%5,%6,%7}, {%8,%9}, {%0,%1,%2,%3};\n"
        : "+f"(d[0]), "+f"(d[1]), "+f"(d[2]), "+f"(d[3])
        : "r"(a0), "r"(a1), "r"(a2), "r"(a3), "r"(b0), "r"(b1));
}

__device__ __forceinline__ uint32_t f2u(float x) { return __float_as_uint(x); }

__global__ __launch_bounds__(256, 2) void mla_attn_tc(
    const float* __restrict__ q, const float* __restrict__ kv,
    const float* __restrict__ kpe, float* __restrict__ out)
{
    extern __shared__ float sm[];
    float* Qs  = sm + OFF_Q;
    float* Ks  = sm + OFF_K;
    float* Vs  = sm + OFF_V;
    float* Ps  = sm + OFF_P;
    float* smM = sm + OFF_M;
    float* smL = sm + OFF_L;
    float* smF = sm + OFF_F;
    float* redM = sm + OFF_RM;
    float* redS = sm + OFF_RS;

    const int h  = blockIdx.y;
    const int qb = gridDim.x - 1 - blockIdx.x;   // heavy tiles first
    const int tid = threadIdx.x;
    const int wid = tid >> 5;
    const int lane = tid & 31;
    const int wr = wid >> 2;      // 0..1
    const int wc = wid & 3;       // 0..3
    const int lq = lane >> 2;     // 0..7
    const int lr = lane & 3;      // 0..3

    const float scale = rsqrtf(192.f);

    // stage Q (raw fp32, scaled)
    for (int idx = tid; idx < 64*192; idx += 256) {
        const int r = idx / 192, d = idx % 192;
        Qs[r*QS + d] = q[(size_t)(qb*64 + r) * QROW + h*QHD + d] * scale;
    }
    if (tid < 64) { smM[tid] = -INFINITY; smL[tid] = 0.f; }

    float Oacc[2][4][4];
#pragma unroll
    for (int mt = 0; mt < 2; mt++)
#pragma unroll
        for (int nt = 0; nt < 4; nt++)
#pragma unroll
            for (int i = 0; i < 4; i++) Oacc[mt][nt][i] = 0.f;

    for (int kb = 0; kb <= qb; kb++) {
        float Sacc[2][2][4];
#pragma unroll
        for (int mt = 0; mt < 2; mt++)
#pragma unroll
            for (int nt = 0; nt < 2; nt++)
#pragma unroll
                for (int i = 0; i < 4; i++) Sacc[mt][nt][i] = 0.f;

        // ---- S = Q K^T over 3 d-chunks of 64
#pragma unroll 1
        for (int c = 0; c < 3; c++) {
            __syncthreads();
            for (int idx = tid; idx < 64*64; idx += 256) {
                const int r = idx >> 6, d = idx & 63;
                const int gd = c*64 + d;
                const float v = (gd < DNOPE)
                    ? kv[(size_t)(kb*64 + r) * KVROW + h*256 + gd]
                    : kpe[(size_t)(kb*64 + r) * DROPE + gd - DNOPE];
                Ks[r*KSS + d] = rna(v);
            }
            __syncthreads();

#pragma unroll
            for (int ks = 0; ks < 8; ks++) {
                const int kof = ks*8 + lr;
                uint32_t b[2][2];
#pragma unroll
                for (int nt = 0; nt < 2; nt++) {
                    const int n = wc*16 + nt*8 + lq;
                    b[nt][0] = f2u(Ks[n*KSS + kof]);
                    b[nt][1] = f2u(Ks[n*KSS + kof + 4]);
                }
#pragma unroll
                for (int mt = 0; mt < 2; mt++) {
                    const int r0 = wr*32 + mt*16 + lq;
                    const int colb = c*64 + kof;
                    const float v0 = Qs[r0*QS + colb];
                    const float v1 = Qs[(r0+8)*QS + colb];
                    const float v2 = Qs[r0*QS + colb + 4];
                    const float v3 = Qs[(r0+8)*QS + colb + 4];
                    const float h0 = rna(v0), h1 = rna(v1);
                    const float h2 = rna(v2), h3 = rna(v3);
                    const float l0 = rna(v0 - h0), l1 = rna(v1 - h1);
                    const float l2 = rna(v2 - h2), l3 = rna(v3 - h3);
#pragma unroll
                    for (int nt = 0; nt < 2; nt++) {
                        mma8(Sacc[mt][nt], f2u(h0), f2u(h1), f2u(h2), f2u(h3),
                             b[nt][0], b[nt][1]);
                        mma8(Sacc[mt][nt], f2u(l0), f2u(l1), f2u(l2), f2u(l3),
                             b[nt][0], b[nt][1]);
                    }
                }
            }
        }

        // ---- softmax: mask + per-thread row maxima
        float tmax[2][2] = { {-INFINITY,-INFINITY}, {-INFINITY,-INFINITY} };
#pragma unroll
        for (int mt = 0; mt < 2; mt++)
#pragma unroll
            for (int nt = 0; nt < 2; nt++)
#pragma unroll
                for (int i = 0; i < 4; i++) {
                    if (kb == qb) {
                        const int row = wr*32 + mt*16 + lq + (i >> 1)*8;
                        const int col = wc*16 + nt*8 + lr*2 + (i & 1);
                        if (col > row) Sacc[mt][nt][i] = -INFINITY;
                    }
                    tmax[mt][i>>1] = fmaxf(tmax[mt][i>>1], Sacc[mt][nt][i]);
                }
#pragma unroll
        for (int mt = 0; mt < 2; mt++)
#pragma unroll
            for (int u = 0; u < 2; u++) {
                float v = tmax[mt][u];
                v = fmaxf(v, __shfl_xor_sync(0xffffffffu, v, 1));
                v = fmaxf(v, __shfl_xor_sync(0xffffffffu, v, 2));
                tmax[mt][u] = v;
            }
        if (lr == 0) {
#pragma unroll
            for (int mt = 0; mt < 2; mt++)
#pragma unroll
                for (int u = 0; u < 2; u++)
                    redM[(wr*32 + mt*16 + lq + u*8)*4 + wc] = tmax[mt][u];
        }
        __syncthreads();

        if (wc == 0 && lr == 0) {
#pragma unroll
            for (int mt = 0; mt < 2; mt++)
#pragma unroll
                for (int u = 0; u < 2; u++) {
                    const int row = wr*32 + mt*16 + lq + u*8;
                    float mx = fmaxf(fmaxf(redM[row*4+0], redM[row*4+1]),
                                     fmaxf(redM[row*4+2], redM[row*4+3]));
                    const float mo = smM[row];
                    const float mn = fmaxf(mo, mx);
                    smM[row] = mn;
                    smF[row] = __expf(mo - mn);
                }
        }
        __syncthreads();

        // p = exp(s - m) -> Ps (raw fp32), partial sums; rescale O
        float mn[2][2];
#pragma unroll
        for (int mt = 0; mt < 2; mt++)
#pragma unroll
            for (int u = 0; u < 2; u++)
                mn[mt][u] = smM[wr*32 + mt*16 + lq + u*8];

        float tsum[2][2] = { {0.f,0.f}, {0.f,0.f} };
#pragma unroll
        for (int mt = 0; mt < 2; mt++)
#pragma unroll
            for (int nt = 0; nt < 2; nt++)
#pragma unroll
                for (int i = 0; i < 4; i++) {
                    const int u = i >> 1;
                    const float p = __expf(Sacc[mt][nt][i] - mn[mt][u]);
                    const int row = wr*32 + mt*16 + lq + u*8;
                    const int col = wc*16 + nt*8 + lr*2 + (i & 1);
                    Ps[row*PSS + col] = p;
                    tsum[mt][u] += p;
                }
#pragma unroll
        for (int mt = 0; mt < 2; mt++)
#pragma unroll
            for (int u = 0; u < 2; u++) {
                float v = tsum[mt][u];
                v += __shfl_xor_sync(0xffffffffu, v, 1);
                v += __shfl_xor_sync(0xffffffffu, v, 2);
                tsum[mt][u] = v;
            }
        if (lr == 0) {
#pragma unroll
            for (int mt = 0; mt < 2; mt++)
#pragma unroll
                for (int u = 0; u < 2; u++)
                    redS[(wr*32 + mt*16 + lq + u*8)*4 + wc] = tsum[mt][u];
        }
        // rescale O accumulators by f
#pragma unroll
        for (int mt = 0; mt < 2; mt++) {
            const int r0 = wr*32 + mt*16 + lq;
            const float f0 = smF[r0], f1 = smF[r0 + 8];
#pragma unroll
            for (int nt = 0; nt < 4; nt++) {
                Oacc[mt][nt][0] *= f0; Oacc[mt][nt][1] *= f0;
                Oacc[mt][nt][2] *= f1; Oacc[mt][nt][3] *= f1;
            }
        }
        __syncthreads();

        if (wc == 0 && lr == 0) {
#pragma unroll
            for (int mt = 0; mt < 2; mt++)
#pragma unroll
                for (int u = 0; u < 2; u++) {
                    const int row = wr*32 + mt*16 + lq + u*8;
                    smL[row] = smL[row]*smF[row] +
                        (redS[row*4+0] + redS[row*4+1] + redS[row*4+2] + redS[row*4+3]);
                }
        }

        // ---- O += P V, V in two 64-col chunks; splits in registers.
        // O column = nt*32 + wc*8 + lr*2 + (i&1); chunk c holds nt in {2c,2c+1}.
#pragma unroll 1
        for (int c = 0; c < 2; c++) {
            __syncthreads();
            for (int idx = tid; idx < 64*64; idx += 256) {
                const int r = idx >> 6, d = idx & 63;
                Vs[r*VSS + d] =
                    kv[(size_t)(kb*64 + r) * KVROW + h*256 + DNOPE + c*64 + d];
            }
            __syncthreads();

#pragma unroll
            for (int ks = 0; ks < 8; ks++) {
                const int k0 = ks*8 + lr;
                uint32_t bh[2][2], bl[2][2];
#pragma unroll
                for (int ntl = 0; ntl < 2; ntl++) {
                    const int nloc = ntl*32 + wc*8 + lq;
                    const float vb0 = Vs[k0*VSS + nloc];
                    const float vb1 = Vs[(k0+4)*VSS + nloc];
                    const float h0 = rna(vb0), h1 = rna(vb1);
                    bh[ntl][0] = f2u(h0);            bh[ntl][1] = f2u(h1);
                    bl[ntl][0] = f2u(rna(vb0 - h0)); bl[ntl][1] = f2u(rna(vb1 - h1));
                }
#pragma unroll
                for (int mt = 0; mt < 2; mt++) {
                    const int r0 = wr*32 + mt*16 + lq;
                    const float p0 = Ps[r0*PSS + k0];
                    const float p1 = Ps[(r0+8)*PSS + k0];
                    const float p2 = Ps[r0*PSS + k0 + 4];
                    const float p3 = Ps[(r0+8)*PSS + k0 + 4];
                    const float ph0 = rna(p0), ph1 = rna(p1);
                    const float ph2 = rna(p2), ph3 = rna(p3);
                    const float pl0 = rna(p0 - ph0), pl1 = rna(p1 - ph1);
                    const float pl2 = rna(p2 - ph2), pl3 = rna(p3 - ph3);
#pragma unroll
                    for (int ntl = 0; ntl < 2; ntl++) {
                        const int nt = c*2 + ntl;
                        mma8(Oacc[mt][nt], f2u(ph0), f2u(ph1), f2u(ph2), f2u(ph3),
                             bh[ntl][0], bh[ntl][1]);
                        mma8(Oacc[mt][nt], f2u(pl0), f2u(pl1), f2u(pl2), f2u(pl3),
                             bh[ntl][0], bh[ntl][1]);
                        mma8(Oacc[mt][nt], f2u(ph0), f2u(ph1), f2u(ph2), f2u(ph3),
                             bl[ntl][0], bl[ntl][1]);
                    }
                }
            }
        }
    }

    __syncthreads();   // smL final

    // epilogue: O/l, tf32-round (feeds wo GEMM), store
#pragma unroll
    for (int mt = 0; mt < 2; mt++) {
        const int r0 = wr*32 + mt*16 + lq;
        const float inv0 = 1.f / smL[r0];
        const float inv1 = 1.f / smL[r0 + 8];
#pragma unroll
        for (int nt = 0; nt < 4; nt++) {
#pragma unroll
            for (int i = 0; i < 4; i++) {
                const int row = (i < 2) ? r0 : (r0 + 8);
                const int col = nt*32 + wc*8 + lr*2 + (i & 1);
                out[(size_t)(qb*64 + row) * HID + h*DVDIM + col] =
                    rna(Oacc[mt][nt][i] * ((i < 2) ? inv0 : inv1));
            }
        }
    }
}

// ---------------------------------------------------------------------------
// Launch
// ---------------------------------------------------------------------------
static inline void launch_tgemm(const float* A, const float* B, float* C,
                                int M, int N, int K)
{
    dim3 grid((N + BN - 1) / BN, M / BM);
    tgemm_k<<<grid, 256, GEMM_SMEM>>>(A, B, C, M, N, K);
}

static inline void launch_round(const float* in, float* out, int n)
{
    const int n4 = n / 4;
    round_copy_k<<<(n4 + 255) / 256, 256>>>(
        (const float4*)in, (float4*)out, n4);
}

extern "C" void kernel_launch(void* const* d_in, const int* in_sizes, int n_in,
                              void* d_out, int out_size)
{
    const float* x        = (const float*)d_in[0];
    const float* wq_a     = (const float*)d_in[1];
    const float* q_a_ln_w = (const float*)d_in[2];
    const float* wq_b     = (const float*)d_in[3];
    const float* wkv_a    = (const float*)d_in[4];
    const float* kv_a_ln_w= (const float*)d_in[5];
    const float* wkv_b    = (const float*)d_in[6];
    const float* wo       = (const float*)d_in[7];
    float* out            = (float*)d_out;

    float *qa, *qbuf, *ckv, *kvn, *kpe, *kv, *attn;
    float *rx, *rwqa, *rwqb, *rwkva, *rwkvb, *rwo;
    cudaGetSymbolAddress((void**)&qa,    g_qa);
    cudaGetSymbolAddress((void**)&qbuf,  g_q);
    cudaGetSymbolAddress((void**)&ckv,   g_ckv);
    cudaGetSymbolAddress((void**)&kvn,   g_kvn);
    cudaGetSymbolAddress((void**)&kpe,   g_kpe);
    cudaGetSymbolAddress((void**)&kv,    g_kv);
    cudaGetSymbolAddress((void**)&attn,  g_attn);
    cudaGetSymbolAddress((void**)&rx,    g_rx);
    cudaGetSymbolAddress((void**)&rwqa,  g_rwqa);
    cudaGetSymbolAddress((void**)&rwqb,  g_rwqb);
    cudaGetSymbolAddress((void**)&rwkva, g_rwkva);
    cudaGetSymbolAddress((void**)&rwkvb, g_rwkvb);
    cudaGetSymbolAddress((void**)&rwo,   g_rwo);

    cudaFuncSetAttribute(tgemm_k,
        cudaFuncAttributeMaxDynamicSharedMemorySize, GEMM_SMEM);
    cudaFuncSetAttribute(mla_attn_tc,
        cudaFuncAttributeMaxDynamicSharedMemorySize, ATTN_SMEM);

    // pre-round GEMM inputs to tf32
    launch_round(x,     rx,    SEQ*HID);
    launch_round(wq_a,  rwqa,  HID*QLORA);
    launch_round(wq_b,  rwqb,  QLORA*QROW);
    launch_round(wkv_a, rwkva, HID*CKVROW);
    launch_round(wkv_b, rwkvb, KVLORA*KVROW);
    launch_round(wo,    rwo,   HID*HID);

    // q path
    launch_tgemm(rx, rwqa, qa, SEQ, QLORA, HID);
    rmsnorm_k<<<SEQ, 256>>>(qa, QLORA, qa, QLORA, QLORA, q_a_ln_w);
    launch_tgemm(qa, rwqb, qbuf, SEQ, QROW, QLORA);

    // kv path
    launch_tgemm(rx, rwkva, ckv, SEQ, CKVROW, HID);
    rmsnorm_k<<<SEQ, 256>>>(ckv, CKVROW, kvn, KVLORA, KVLORA, kv_a_ln_w);
    rope_k_k<<<SEQ, 32>>>(ckv, kpe);
    launch_tgemm(kvn, rwkvb, kv, SEQ, KVROW, KVLORA);

    // rope q (in place)
    rope_q_k<<<SEQ, 512>>>(qbuf);

    // attention (writes tf32-rounded output)
    dim3 agrid(SEQ / 64, NHEADS);
    mla_attn_tc<<<agrid, 256, ATTN_SMEM>>>(qbuf, kv, kpe, attn);

    // output projection
    launch_tgemm(attn, rwo, out, SEQ, HID, NHEADS * DVDIM);
}

// round 7
// speedup vs baseline: 1.9990x; 1.0031x over previous
#include <cuda_runtime.h>
#include <cuda_bf16.h>
#include <mma.h>
#include <math.h>
#include <stdint.h>

using namespace nvcuda;

// ---------------------------------------------------------------------------
// Problem constants
// ---------------------------------------------------------------------------
#define SEQ     2048
#define HID     2048
#define NHEADS  16
#define QLORA   1536
#define KVLORA  512
#define DROPE   64
#define DNOPE   128
#define DVDIM   128
#define QHD     192
#define QROW    (NHEADS*QHD)            // 3072
#define KVROW   (NHEADS*(DNOPE+DVDIM))  // 4096
#define CKVROW  (KVLORA+DROPE)          // 576

// ---------------------------------------------------------------------------
// Scratch (device globals)
// ---------------------------------------------------------------------------
__device__ float g_qa  [SEQ*QLORA];
__device__ float g_q   [SEQ*QROW];
__device__ float g_ckv [SEQ*CKVROW];
__device__ float g_kvn [SEQ*KVLORA];
__device__ float g_kpe [SEQ*DROPE];
__device__ float g_kv  [SEQ*KVROW];
__device__ float g_attn[SEQ*HID];
// tf32-rounded copies of GEMM inputs
__device__ float g_rx   [SEQ*HID];
__device__ float g_rwqa [HID*QLORA];
__device__ float g_rwqb [QLORA*QROW];
__device__ float g_rwkva[HID*CKVROW];
__device__ float g_rwkvb[KVLORA*KVROW];
__device__ float g_rwo  [HID*HID];

__device__ __forceinline__ float rna(float x) {
    uint32_t r;
    asm("cvt.rna.tf32.f32 %0, %1;" : "=r"(r) : "f"(x));
    return __uint_as_float(r);
}

// ---------------------------------------------------------------------------
// elementwise tf32 round copy (float4)
// ---------------------------------------------------------------------------
__global__ __launch_bounds__(256) void round_copy_k(
    const float4* __restrict__ in, float4* __restrict__ out, int n4)
{
    int i = blockIdx.x * 256 + threadIdx.x;
    if (i < n4) {
        float4 v = in[i];
        v.x = rna(v.x); v.y = rna(v.y); v.z = rna(v.z); v.w = rna(v.w);
        out[i] = v;
    }
}

// ---------------------------------------------------------------------------
// TF32 wmma GEMM with cp.async 4-stage pipeline.
// C[M,N] = A[M,K]*B[K,N], A/B pre-rounded to tf32 values.
// M%128==0, K%32==0 (K/32 >= 3), N%4==0.
// ---------------------------------------------------------------------------
#define BM 128
#define BN 128
#define BK 32
#define AS_LD 36
#define BS_LD 132
#define STAGE_F (BM*AS_LD + BK*BS_LD)   // 8832 floats
#define NSTAGE 4
#define GEMM_SMEM (NSTAGE*STAGE_F*4)    // 141312 B

__global__ __launch_bounds__(256) void tgemm_k(
    const float* __restrict__ A, const float* __restrict__ B,
    float* __restrict__ C, int M, int N, int K)
{
    extern __shared__ float smem[];
    const int tid = threadIdx.x;
    const int warpId = tid >> 5;
    const int wr = warpId >> 2;
    const int wc = warpId & 3;
    const int br = blockIdx.y * BM;
    const int bc = blockIdx.x * BN;

    wmma::fragment<wmma::accumulator, 16, 16, 8, float> acc[4][2];
#pragma unroll
    for (int i = 0; i < 4; i++)
#pragma unroll
        for (int j = 0; j < 2; j++)
            wmma::fill_fragment(acc[i][j], 0.f);

    auto issue = [&](int k0, int st) {
        float* As = smem + st * STAGE_F;
        float* Bs = As + BM * AS_LD;
#pragma unroll
        for (int i = 0; i < 4; i++) {
            const int lin = i * 256 + tid;
            const int r = lin >> 3, c = (lin & 7) << 2;
            uint32_t dst = (uint32_t)__cvta_generic_to_shared(&As[r*AS_LD + c]);
            const float* src = &A[(size_t)(br + r) * K + k0 + c];
            asm volatile("cp.async.cg.shared.global [%0], [%1], 16;\n"
                         :: "r"(dst), "l"(src));
        }
#pragma unroll
        for (int i = 0; i < 4; i++) {
            const int lin = i * 256 + tid;
            const int r = lin >> 5, c = (lin & 31) << 2;
            const int gc = bc + c;
            uint32_t dst = (uint32_t)__cvta_generic_to_shared(&Bs[r*BS_LD + c]);
            const float* src = &B[(size_t)(k0 + r) * N + gc];
            const int sz = (gc < N) ? 16 : 0;
            asm volatile("cp.async.cg.shared.global [%0], [%1], 16, %2;\n"
                         :: "r"(dst), "l"(src), "r"(sz));
        }
        asm volatile("cp.async.commit_group;\n");
    };

    const int nsteps = K / BK;
    issue(0, 0);
    if (nsteps > 1) issue(BK, 1);
    if (nsteps > 2) issue(2*BK, 2);

    for (int s = 0; s < nsteps; s++) {
        asm volatile("cp.async.wait_group 2;\n");
        __syncthreads();
        if (s + 3 < nsteps) issue((s + 3) * BK, (s + 3) % NSTAGE);

        const float* As = smem + (s % NSTAGE) * STAGE_F;
        const float* Bs = As + BM * AS_LD;
#pragma unroll
        for (int kk = 0; kk < BK; kk += 8) {
            wmma::fragment<wmma::matrix_a, 16, 16, 8,
                           wmma::precision::tf32, wmma::row_major> af[4];
            wmma::fragment<wmma::matrix_b, 16, 16, 8,
                           wmma::precision::tf32, wmma::row_major> bf[2];
#pragma unroll
            for (int i = 0; i < 4; i++)
                wmma::load_matrix_sync(af[i], &As[(wr*64 + i*16)*AS_LD + kk], AS_LD);
#pragma unroll
            for (int j = 0; j < 2; j++)
                wmma::load_matrix_sync(bf[j], &Bs[kk*BS_LD + wc*32 + j*16], BS_LD);
#pragma unroll
            for (int i = 0; i < 4; i++)
#pragma unroll
                for (int j = 0; j < 2; j++)
                    wmma::mma_sync(acc[i][j], af[i], bf[j], acc[i][j]);
        }
        __syncthreads();
    }

#pragma unroll
    for (int i = 0; i < 4; i++) {
        const int gr = br + wr*64 + i*16;
#pragma unroll
        for (int j = 0; j < 2; j++) {
            const int gc = bc + wc*32 + j*16;
            if (gc < N)
                wmma::store_matrix_sync(&C[(size_t)gr * N + gc], acc[i][j],
                                        N, wmma::mem_row_major);
        }
    }
}

// ---------------------------------------------------------------------------
// RMSNorm (output tf32-rounded: feeds a GEMM)
// ---------------------------------------------------------------------------
__global__ __launch_bounds__(256) void rmsnorm_k(
    const float* __restrict__ in, int istride,
    float* __restrict__ out, int ostride,
    int dim, const float* __restrict__ w)
{
    const int row = blockIdx.x;
    const float* x = in + (size_t)row * istride;
    float* y = out + (size_t)row * ostride;

    float ss = 0.f;
    for (int i = threadIdx.x; i < dim; i += blockDim.x) {
        float v = x[i];
        ss = fmaf(v, v, ss);
    }
#pragma unroll
    for (int o = 16; o; o >>= 1) ss += __shfl_xor_sync(0xffffffffu, ss, o);

    __shared__ float red[8];
    if ((threadIdx.x & 31) == 0) red[threadIdx.x >> 5] = ss;
    __syncthreads();
    __shared__ float s_rstd;
    if (threadIdx.x == 0) {
        float v = 0.f;
        for (int i = 0; i < 8; i++) v += red[i];
        s_rstd = rsqrtf(v / (float)dim + 1e-6f);
    }
    __syncthreads();
    const float rstd = s_rstd;
    for (int i = threadIdx.x; i < dim; i += blockDim.x)
        y[i] = rna(x[i] * rstd * w[i]);
}

// ---------------------------------------------------------------------------
// RoPE kernels
// ---------------------------------------------------------------------------
__global__ __launch_bounds__(512) void rope_q_k(float* __restrict__ q)
{
    const int t = blockIdx.x;
    const int h = threadIdx.x >> 5;
    const int i = threadIdx.x & 31;
    const float inv = powf(10000.f, -(float)i / 32.f);
    float s, c;
    sincosf((float)t * inv, &s, &c);
    float* base = q + (size_t)t * QROW + h * QHD + DNOPE;
    const float x1 = base[i];
    const float x2 = base[i + 32];
    base[i]      = x1 * c - x2 * s;
    base[i + 32] = x2 * c + x1 * s;
}

__global__ __launch_bounds__(32) void rope_k_k(
    const float* __restrict__ ckv, float* __restrict__ kpe)
{
    const int t = blockIdx.x;
    const int i = threadIdx.x;
    const float inv = powf(10000.f, -(float)i / 32.f);
    float s, c;
    sincosf((float)t * inv, &s, &c);
    const float x1 = ckv[(size_t)t * CKVROW + KVLORA + i];
    const float x2 = ckv[(size_t)t * CKVROW + KVLORA + 32 + i];
    kpe[(size_t)t * DROPE + i]      = x1 * c - x2 * s;
    kpe[(size_t)t * DROPE + 32 + i] = x2 * c + x1 * s;
}

// ---------------------------------------------------------------------------
// Tensor-core flash attention (causal), tf32 mma.m16n8k8.
// Precision: S = (Qhi+Qlo)*K ; O += Phi*Vhi + Plo*Vhi + Phi*Vlo,
// hi/lo splits in registers from single fp32 smem copies.
// V chunk-0 prefetched via cp.async during the QK phase.
// ---------------------------------------------------------------------------
#define QS  196
#define KSS 68
#define VSS 72
#define PSS 68

#define OFF_Q  0
#define OFF_K  (OFF_Q + 64*QS)
#define OFF_V  (OFF_K + 64*KSS)
#define OFF_P  (OFF_V + 64*VSS)
#define OFF_M  (OFF_P + 64*PSS)
#define OFF_L  (OFF_M + 64)
#define OFF_F  (OFF_L + 64)
#define OFF_RM (OFF_F + 64)
#define OFF_RS (OFF_RM + 256)
#define ATTN_F (OFF_RS + 256)
#define ATTN_SMEM (ATTN_F*4)

__device__ __forceinline__ void mma8(float* d,
    uint32_t a0, uint32_t a1, uint32_t a2, uint32_t a3,
    uint32_t b0, uint32_t b1)
{
    asm volatile(
        "mma.sync.aligned.m16n8k8.row.col.f32.tf32.tf32.f32 "
        "{%0,%1,%2,%3}, {%4,%5,%6,%7}, {%8,%9}, {%0,%1,%2,%3};\n"
        : "+f"(d[0]), "+f"(d[1]), "+f"(d[2]), "+f"(d[3])
        : "r"(a0), "r"(a1), "r"(a2), "r"(a3), "r"(b0), "r"(b1));
}

__device__ __forceinline__ uint32_t f2u(float x) { return __float_as_uint(x); }

__global__ __launch_bounds__(256, 2) void mla_attn_tc(
    const float* __restrict__ q, const float* __restrict__ kv,
    const float* __restrict__ kpe, float* __restrict__ out)
{
    extern __shared__ float sm[];
    float* Qs  = sm + OFF_Q;
    float* Ks  = sm + OFF_K;
    float* Vs  = sm + OFF_V;
    float* Ps  = sm + OFF_P;
    float* smM = sm + OFF_M;
    float* smL = sm + OFF_L;
    float* smF = sm + OFF_F;
    float* redM = sm + OFF_RM;
    float* redS = sm + OFF_RS;

    const int h  = blockIdx.y;
    const int qb = gridDim.x - 1 - blockIdx.x;   // heavy tiles first
    const int tid = threadIdx.x;
    const int wid = tid >> 5;
    const int lane = tid & 31;
    const int wr = wid >> 2;      // 0..1
    const int wc = wid & 3;       // 0..3
    const int lq = lane >> 2;     // 0..7
    const int lr = lane & 3;      // 0..3

    const float scale = rsqrtf(192.f);

    // stage Q (raw fp32, scaled)
    for (int idx = tid; idx < 64*192; idx += 256) {
        const int r = idx / 192, d = idx % 192;
        Qs[r*QS + d] = q[(size_t)(qb*64 + r) * QROW + h*QHD + d] * scale;
    }
    if (tid < 64) { smM[tid] = -INFINITY; smL[tid] = 0.f; }

    float Oacc[2][4][4];
#pragma unroll
    for (int mt = 0; mt < 2; mt++)
#pragma unroll
        for (int nt = 0; nt < 4; nt++)
#pragma unroll
            for (int i = 0; i < 4; i++) Oacc[mt][nt][i] = 0.f;

    for (int kb = 0; kb <= qb; kb++) {
        // Vs free (prior PV chunk-1 mma done by all warps after this barrier)
        __syncthreads();
        // prefetch V chunk 0 into Vs via cp.async (overlaps the QK phase)
        {
#pragma unroll
            for (int i = 0; i < 4; i++) {
                const int lin = i * 256 + tid;
                const int r = lin >> 4;            // 0..63
                const int c = (lin & 15) << 2;     // 0..60
                uint32_t dst = (uint32_t)__cvta_generic_to_shared(&Vs[r*VSS + c]);
                const float* src =
                    &kv[(size_t)(kb*64 + r) * KVROW + h*256 + DNOPE + c];
                asm volatile("cp.async.cg.shared.global [%0], [%1], 16;\n"
                             :: "r"(dst), "l"(src));
            }
            asm volatile("cp.async.commit_group;\n");
        }

        float Sacc[2][2][4];
#pragma unroll
        for (int mt = 0; mt < 2; mt++)
#pragma unroll
            for (int nt = 0; nt < 2; nt++)
#pragma unroll
                for (int i = 0; i < 4; i++) Sacc[mt][nt][i] = 0.f;

        // ---- S = Q K^T over 3 d-chunks of 64
#pragma unroll 1
        for (int c = 0; c < 3; c++) {
            if (c) __syncthreads();
            for (int idx = tid; idx < 64*64; idx += 256) {
                const int r = idx >> 6, d = idx & 63;
                const int gd = c*64 + d;
                const float v = (gd < DNOPE)
                    ? kv[(size_t)(kb*64 + r) * KVROW + h*256 + gd]
                    : kpe[(size_t)(kb*64 + r) * DROPE + gd - DNOPE];
                Ks[r*KSS + d] = rna(v);
            }
            __syncthreads();

#pragma unroll
            for (int ks = 0; ks < 8; ks++) {
                const int kof = ks*8 + lr;
                uint32_t b[2][2];
#pragma unroll
                for (int nt = 0; nt < 2; nt++) {
                    const int n = wc*16 + nt*8 + lq;
                    b[nt][0] = f2u(Ks[n*KSS + kof]);
                    b[nt][1] = f2u(Ks[n*KSS + kof + 4]);
                }
#pragma unroll
                for (int mt = 0; mt < 2; mt++) {
                    const int r0 = wr*32 + mt*16 + lq;
                    const int colb = c*64 + kof;
                    const float v0 = Qs[r0*QS + colb];
                    const float v1 = Qs[(r0+8)*QS + colb];
                    const float v2 = Qs[r0*QS + colb + 4];
                    const float v3 = Qs[(r0+8)*QS + colb + 4];
                    const float h0 = rna(v0), h1 = rna(v1);
                    const float h2 = rna(v2), h3 = rna(v3);
                    const float l0 = rna(v0 - h0), l1 = rna(v1 - h1);
                    const float l2 = rna(v2 - h2), l3 = rna(v3 - h3);
#pragma unroll
                    for (int nt = 0; nt < 2; nt++) {
                        mma8(Sacc[mt][nt], f2u(h0), f2u(h1), f2u(h2), f2u(h3),
                             b[nt][0], b[nt][1]);
                        mma8(Sacc[mt][nt], f2u(l0), f2u(l1), f2u(l2), f2u(l3),
                             b[nt][0], b[nt][1]);
                    }
                }
            }
        }

        // ---- softmax: mask + per-thread row maxima
        float tmax[2][2] = { {-INFINITY,-INFINITY}, {-INFINITY,-INFINITY} };
#pragma unroll
        for (int mt = 0; mt < 2; mt++)
#pragma unroll
            for (int nt = 0; nt < 2; nt++)
#pragma unroll
                for (int i = 0; i < 4; i++) {
                    if (kb == qb) {
                        const int row = wr*32 + mt*16 + lq + (i >> 1)*8;
                        const int col = wc*16 + nt*8 + lr*2 + (i & 1);
                        if (col > row) Sacc[mt][nt][i] = -INFINITY;
                    }
                    tmax[mt][i>>1] = fmaxf(tmax[mt][i>>1], Sacc[mt][nt][i]);
                }
#pragma unroll
        for (int mt = 0; mt < 2; mt++)
#pragma unroll
            for (int u = 0; u < 2; u++) {
                float v = tmax[mt][u];
                v = fmaxf(v, __shfl_xor_sync(0xffffffffu, v, 1));
                v = fmaxf(v, __shfl_xor_sync(0xffffffffu, v, 2));
                tmax[mt][u] = v;
            }
        if (lr == 0) {
#pragma unroll
            for (int mt = 0; mt < 2; mt++)
#pragma unroll
                for (int u = 0; u < 2; u++)
                    redM[(wr*32 + mt*16 + lq + u*8)*4 + wc] = tmax[mt][u];
        }
        __syncthreads();

        if (wc == 0 && lr == 0) {
#pragma unroll
            for (int mt = 0; mt < 2; mt++)
#pragma unroll
                for (int u = 0; u < 2; u++) {
                    const int row = wr*32 + mt*16 + lq + u*8;
                    float mx = fmaxf(fmaxf(redM[row*4+0], redM[row*4+1]),
                                     fmaxf(redM[row*4+2], redM[row*4+3]));
                    const float mo = smM[row];
                    const float mn = fmaxf(mo, mx);
                    smM[row] = mn;
                    smF[row] = __expf(mo - mn);
                }
        }
        __syncthreads();

        // p = exp(s - m) -> Ps (raw fp32), partial sums; rescale O
        float mn[2][2];
#pragma unroll
        for (int mt = 0; mt < 2; mt++)
#pragma unroll
            for (int u = 0; u < 2; u++)
                mn[mt][u] = smM[wr*32 + mt*16 + lq + u*8];

        float tsum[2][2] = { {0.f,0.f}, {0.f,0.f} };
#pragma unroll
        for (int mt = 0; mt < 2; mt++)
#pragma unroll
            for (int nt = 0; nt < 2; nt++)
#pragma unroll
                for (int i = 0; i < 4; i++) {
                    const int u = i >> 1;
                    const float p = __expf(Sacc[mt][nt][i] - mn[mt][u]);
                    const int row = wr*32 + mt*16 + lq + u*8;
                    const int col = wc*16 + nt*8 + lr*2 + (i & 1);
                    Ps[row*PSS + col] = p;
                    tsum[mt][u] += p;
                }
#pragma unroll
        for (int mt = 0; mt < 2; mt++)
#pragma unroll
            for (int u = 0; u < 2; u++) {
                float v = tsum[mt][u];
                v += __shfl_xor_sync(0xffffffffu, v, 1);
                v += __shfl_xor_sync(0xffffffffu, v, 2);
                tsum[mt][u] = v;
            }
        if (lr == 0) {
#pragma unroll
            for (int mt = 0; mt < 2; mt++)
#pragma unroll
                for (int u = 0; u < 2; u++)
                    redS[(wr*32 + mt*16 + lq + u*8)*4 + wc] = tsum[mt][u];
        }
        // rescale O accumulators by f
#pragma unroll
        for (int mt = 0; mt < 2; mt++) {
            const int r0 = wr*32 + mt*16 + lq;
            const float f0 = smF[r0], f1 = smF[r0 + 8];
#pragma unroll
            for (int nt = 0; nt < 4; nt++) {
                Oacc[mt][nt][0] *= f0; Oacc[mt][nt][1] *= f0;
                Oacc[mt][nt][2] *= f1; Oacc[mt][nt][3] *= f1;
            }
        }
        __syncthreads();

        if (wc == 0 && lr == 0) {
#pragma unroll
            for (int mt = 0; mt < 2; mt++)
#pragma unroll
                for (int u = 0; u < 2; u++) {
                    const int row = wr*32 + mt*16 + lq + u*8;
                    smL[row] = smL[row]*smF[row] +
                        (redS[row*4+0] + redS[row*4+1] + redS[row*4+2] + redS[row*4+3]);
                }
        }

        // ---- O += P V, V in two 64-col chunks; splits in registers.
        // O column = nt*32 + wc*8 + lr*2 + (i&1); chunk c holds nt in {2c,2c+1}.
#pragma unroll 1
        for (int c = 0; c < 2; c++) {
            if (c == 0) {
                // V chunk 0 arrived via cp.async (issued at kb start)
                asm volatile("cp.async.wait_group 0;\n");
                __syncthreads();
            } else {
                __syncthreads();
                for (int idx = tid; idx < 64*64; idx += 256) {
                    const int r = idx >> 6, d = idx & 63;
                    Vs[r*VSS + d] =
                        kv[(size_t)(kb*64 + r) * KVROW + h*256 + DNOPE + 64 + d];
                }
                __syncthreads();
            }

#pragma unroll
            for (int ks = 0; ks < 8; ks++) {
                const int k0 = ks*8 + lr;
                uint32_t bh[2][2], bl[2][2];
#pragma unroll
                for (int ntl = 0; ntl < 2; ntl++) {
                    const int nloc = ntl*32 + wc*8 + lq;
                    const float vb0 = Vs[k0*VSS + nloc];
                    const float vb1 = Vs[(k0+4)*VSS + nloc];
                    const float h0 = rna(vb0), h1 = rna(vb1);
                    bh[ntl][0] = f2u(h0);            bh[ntl][1] = f2u(h1);
                    bl[ntl][0] = f2u(rna(vb0 - h0)); bl[ntl][1] = f2u(rna(vb1 - h1));
                }
#pragma unroll
                for (int mt = 0; mt < 2; mt++) {
                    const int r0 = wr*32 + mt*16 + lq;
                    const float p0 = Ps[r0*PSS + k0];
                    const float p1 = Ps[(r0+8)*PSS + k0];
                    const float p2 = Ps[r0*PSS + k0 + 4];
                    const float p3 = Ps[(r0+8)*PSS + k0 + 4];
                    const float ph0 = rna(p0), ph1 = rna(p1);
                    const float ph2 = rna(p2), ph3 = rna(p3);
                    const float pl0 = rna(p0 - ph0), pl1 = rna(p1 - ph1);
                    const float pl2 = rna(p2 - ph2), pl3 = rna(p3 - ph3);
#pragma unroll
                    for (int ntl = 0; ntl < 2; ntl++) {
                        const int nt = c*2 + ntl;
                        mma8(Oacc[mt][nt], f2u(ph0), f2u(ph1), f2u(ph2), f2u(ph3),
                             bh[ntl][0], bh[ntl][1]);
                        mma8(Oacc[mt][nt], f2u(pl0), f2u(pl1), f2u(pl2), f2u(pl3),
                             bh[ntl][0], bh[ntl][1]);
                        mma8(Oacc[mt][nt], f2u(ph0), f2u(ph1), f2u(ph2), f2u(ph3),
                             bl[ntl][0], bl[ntl][1]);
                    }
                }
            }
        }
    }

    __syncthreads();   // smL final

    // epilogue: O/l, tf32-round (feeds wo GEMM), store
#pragma unroll
    for (int mt = 0; mt < 2; mt++) {
        const int r0 = wr*32 + mt*16 + lq;
        const float inv0 = 1.f / smL[r0];
        const float inv1 = 1.f / smL[r0 + 8];
#pragma unroll
        for (int nt = 0; nt < 4; nt++) {
#pragma unroll
            for (int i = 0; i < 4; i++) {
                const int row = (i < 2) ? r0 : (r0 + 8);
                const int col = nt*32 + wc*8 + lr*2 + (i & 1);
                out[(size_t)(qb*64 + row) * HID + h*DVDIM + col] =
                    rna(Oacc[mt][nt][i] * ((i < 2) ? inv0 : inv1));
            }
        }
    }
}

// ---------------------------------------------------------------------------
// Launch
// ---------------------------------------------------------------------------
static inline void launch_tgemm(const float* A, const float* B, float* C,
                                int M, int N, int K)
{
    dim3 grid((N + BN - 1) / BN, M / BM);
    tgemm_k<<<grid, 256, GEMM_SMEM>>>(A, B, C, M, N, K);
}

static inline void launch_round(const float* in, float* out, int n)
{
    const int n4 = n / 4;
    round_copy_k<<<(n4 + 255) / 256, 256>>>(
        (const float4*)in, (float4*)out, n4);
}

extern "C" void kernel_launch(void* const* d_in, const int* in_sizes, int n_in,
                              void* d_out, int out_size)
{
    const float* x        = (const float*)d_in[0];
    const float* wq_a     = (const float*)d_in[1];
    const float* q_a_ln_w = (const float*)d_in[2];
    const float* wq_b     = (const float*)d_in[3];
    const float* wkv_a    = (const float*)d_in[4];
    const float* kv_a_ln_w= (const float*)d_in[5];
    const float* wkv_b    = (const float*)d_in[6];
    const float* wo       = (const float*)d_in[7];
    float* out            = (float*)d_out;

    float *qa, *qbuf, *ckv, *kvn, *kpe, *kv, *attn;
    float *rx, *rwqa, *rwqb, *rwkva, *rwkvb, *rwo;
    cudaGetSymbolAddress((void**)&qa,    g_qa);
    cudaGetSymbolAddress((void**)&qbuf,  g_q);
    cudaGetSymbolAddress((void**)&ckv,   g_ckv);
    cudaGetSymbolAddress((void**)&kvn,   g_kvn);
    cudaGetSymbolAddress((void**)&kpe,   g_kpe);
    cudaGetSymbolAddress((void**)&kv,    g_kv);
    cudaGetSymbolAddress((void**)&attn,  g_attn);
    cudaGetSymbolAddress((void**)&rx,    g_rx);
    cudaGetSymbolAddress((void**)&rwqa,  g_rwqa);
    cudaGetSymbolAddress((void**)&rwqb,  g_rwqb);
    cudaGetSymbolAddress((void**)&rwkva, g_rwkva);
    cudaGetSymbolAddress((void**)&rwkvb, g_rwkvb);
    cudaGetSymbolAddress((void**)&rwo,   g_rwo);

    cudaFuncSetAttribute(tgemm_k,
        cudaFuncAttributeMaxDynamicSharedMemorySize, GEMM_SMEM);
    cudaFuncSetAttribute(mla_attn_tc,
        cudaFuncAttributeMaxDynamicSharedMemorySize, ATTN_SMEM);

    // Launch order chosen so ncu's "-s 5 -c 1" capture lands on the
    // biggest GEMM (qa @ wq_b, launch index 5).
    launch_round(x,     rx,    SEQ*HID);                         // 0
    launch_round(wq_a,  rwqa,  HID*QLORA);                       // 1
    launch_tgemm(rx, rwqa, qa, SEQ, QLORA, HID);                 // 2
    rmsnorm_k<<<SEQ, 256>>>(qa, QLORA, qa, QLORA, QLORA, q_a_ln_w); // 3
    launch_round(wq_b,  rwqb,  QLORA*QROW);                      // 4
    launch_tgemm(qa, rwqb, qbuf, SEQ, QROW, QLORA);              // 5 <- profiled

    // kv path
    launch_round(wkv_a, rwkva, HID*CKVROW);
    launch_tgemm(rx, rwkva, ckv, SEQ, CKVROW, HID);
    rmsnorm_k<<<SEQ, 256>>>(ckv, CKVROW, kvn, KVLORA, KVLORA, kv_a_ln_w);
    rope_k_k<<<SEQ, 32>>>(ckv, kpe);
    launch_round(wkv_b, rwkvb, KVLORA*KVROW);
    launch_tgemm(kvn, rwkvb, kv, SEQ, KVROW, KVLORA);

    // rope q (in place)
    rope_q_k<<<SEQ, 512>>>(qbuf);

    // attention (writes tf32-rounded output)
    dim3 agrid(SEQ / 64, NHEADS);
    mla_attn_tc<<<agrid, 256, ATTN_SMEM>>>(qbuf, kv, kpe, attn);

    // output projection
    launch_round(wo, rwo, HID*HID);
    launch_tgemm(attn, rwo, out, SEQ, HID, NHEADS * DVDIM);
}